// round 7
// baseline (speedup 1.0000x reference)
#include <cuda_runtime.h>
#include <cuda_bf16.h>
#include <math.h>
#include <stdint.h>

// ---------------------------------------------------------------------------
// Problem constants
// ---------------------------------------------------------------------------
#define B_    2
#define N_    8192
#define C_    2048
#define H_    16
#define HD_   128
#define GS_   256
#define G_    (N_/GS_)     // 32
#define HALF_ 8
#define SHIFT_ 128
#define SCALE_ 0.08838834764831843f   // 1/sqrt(128)
#define NEGF  -1e9f

#define MROWS (B_*N_)      // 16384
#define K6    (3*C_)       // 6144 augmented K: [hi|lo|hi] x [hi|hi|lo]

// scratch
__device__ __nv_bfloat16 g_A[(size_t)MROWS * K6];            // x_aug  [16384][6144]
__device__ __nv_bfloat16 g_B[(size_t)3 * C_ * K6];           // W_aug  [3][2048][6144]
__device__ __nv_bfloat16 g_hi[(size_t)3 * B_ * H_ * N_ * HD_];  // qkv hi (shifted)
__device__ __nv_bfloat16 g_lo[(size_t)3 * B_ * H_ * N_ * HD_];  // qkv lo (shifted)

// ---------------------------------------------------------------------------
// split: fp32 [rows][2048] -> bf16 [rows][6144]; hi at col 0 and hi2_off, lo at lo_off
// ---------------------------------------------------------------------------
__global__ __launch_bounds__(256) void split_kernel(
    const float* __restrict__ in, __nv_bfloat16* __restrict__ out,
    int hi2_off, int lo_off)
{
    size_t idx = (size_t)blockIdx.x * 256 + threadIdx.x;   // one float4 each
    float4 v = ((const float4*)in)[idx];
    size_t m  = idx >> 9;          // 512 float4 per row
    int    c  = (int)(idx & 511) * 4;

    __nv_bfloat16 h0 = __float2bfloat16(v.x);
    __nv_bfloat16 h1 = __float2bfloat16(v.y);
    __nv_bfloat16 h2 = __float2bfloat16(v.z);
    __nv_bfloat16 h3 = __float2bfloat16(v.w);
    __nv_bfloat16 l0 = __float2bfloat16(v.x - __bfloat162float(h0));
    __nv_bfloat16 l1 = __float2bfloat16(v.y - __bfloat162float(h1));
    __nv_bfloat16 l2 = __float2bfloat16(v.z - __bfloat162float(h2));
    __nv_bfloat16 l3 = __float2bfloat16(v.w - __bfloat162float(h3));

    __nv_bfloat162 hA(h0, h1), hB(h2, h3), lA(l0, l1), lB(l2, l3);
    __nv_bfloat16* rowp = out + m * K6;
    *(__nv_bfloat162*)(rowp + c)               = hA;
    *(__nv_bfloat162*)(rowp + c + 2)           = hB;
    *(__nv_bfloat162*)(rowp + hi2_off + c)     = hA;
    *(__nv_bfloat162*)(rowp + hi2_off + c + 2) = hB;
    *(__nv_bfloat162*)(rowp + lo_off + c)      = lA;
    *(__nv_bfloat162*)(rowp + lo_off + c + 2)  = lB;
}

// ---------------------------------------------------------------------------
// common MMA helpers (proven in R5/R6)
// ---------------------------------------------------------------------------
__device__ __forceinline__ uint32_t s2u(const void* p) {
    uint32_t a;
    asm("{ .reg .u64 t; cvta.to.shared.u64 t, %1; cvt.u32.u64 %0, t; }"
        : "=r"(a) : "l"(p));
    return a;
}
__device__ __forceinline__ void ldmx4(uint32_t* r, uint32_t addr) {
    asm volatile("ldmatrix.sync.aligned.m8n8.x4.shared.b16 {%0,%1,%2,%3}, [%4];"
                 : "=r"(r[0]), "=r"(r[1]), "=r"(r[2]), "=r"(r[3]) : "r"(addr));
}
__device__ __forceinline__ void ldmx4t(uint32_t* r, uint32_t addr) {
    asm volatile("ldmatrix.sync.aligned.m8n8.x4.trans.shared.b16 {%0,%1,%2,%3}, [%4];"
                 : "=r"(r[0]), "=r"(r[1]), "=r"(r[2]), "=r"(r[3]) : "r"(addr));
}
__device__ __forceinline__ void mma16816(float* c, const uint32_t* a,
                                         uint32_t b0, uint32_t b1) {
    asm volatile(
        "mma.sync.aligned.m16n8k16.row.col.f32.bf16.bf16.f32 "
        "{%0,%1,%2,%3}, {%4,%5,%6,%7}, {%8,%9}, {%0,%1,%2,%3};"
        : "+f"(c[0]), "+f"(c[1]), "+f"(c[2]), "+f"(c[3])
        : "r"(a[0]), "r"(a[1]), "r"(a[2]), "r"(a[3]), "r"(b0), "r"(b1));
}
__device__ __forceinline__ void cp16(uint32_t dst, const void* src) {
    asm volatile("cp.async.cg.shared.global [%0], [%1], 16;"
                 :: "r"(dst), "l"(src) : "memory");
}

// ---------------------------------------------------------------------------
// HMMA GEMM v2: tile 128x256, warp tile 64x64, 3-stage cp.async pipeline.
// D[m,n] = sum_k A[m,k]*B[n,k], K=6144 augmented. Epilogue -> bf16 hi/lo qkv.
// smem stage: A 128x(32+8pad) + B 256x(32+8pad) bf16 = 30720 B; x3 = 92160 B
// ---------------------------------------------------------------------------
#define KC      32
#define NCH     (K6/KC)        // 192
#define ROWB    80             // padded row bytes (32 bf16 + 8 pad)
#define STAGE_B (128*ROWB + 256*ROWB)   // 30720
#define GM_SMEM (3*STAGE_B)    // 92160

__global__ __launch_bounds__(256, 1) void gemm_kernel(
    const float* __restrict__ bq, const float* __restrict__ bk,
    const float* __restrict__ bv)
{
    extern __shared__ char smg[];
    const uint32_t smb = s2u(smg);

    const int tid  = threadIdx.x;
    const int wid  = tid >> 5, lane = tid & 31;
    const int wm   = wid & 1;          // 2 warp rows x 64
    const int wn   = wid >> 1;         // 4 warp cols x 64
    const int lrow = lane & 15;
    const int lcol = (lane >> 4) * 8;

    const int n0 = blockIdx.x * 256;   // n fastest: B panels stay hot in L2
    const int m0 = blockIdx.y * 128;
    const int z  = blockIdx.z;
    const __nv_bfloat16* __restrict__ Ap = g_A + (size_t)m0 * K6;
    const __nv_bfloat16* __restrict__ Bp = g_B + (size_t)z * C_ * K6 + (size_t)n0 * K6;
    const float* __restrict__ bias = (z == 0) ? bq : (z == 1) ? bk : bv;

    float acc[4][8][4];
    #pragma unroll
    for (int i = 0; i < 4; i++)
        #pragma unroll
        for (int j = 0; j < 8; j++)
            #pragma unroll
            for (int k = 0; k < 4; k++) acc[i][j][k] = 0.f;

    // ---- async fetch of chunk c into stage c%3 ----
    auto fetch = [&](int c) {
        const int s = c - (c / 3) * 3;
        const size_t k0 = (size_t)c * KC;
        uint32_t base = smb + s * STAGE_B;
        #pragma unroll
        for (int i = 0; i < 2; i++) {           // A: 128 rows x 64B
            int f = tid + 256 * i, row = f >> 2, cc = (f & 3) * 16;
            cp16(base + row * ROWB + cc, Ap + (size_t)row * K6 + k0 + cc / 2);
        }
        base += 128 * ROWB;
        #pragma unroll
        for (int i = 0; i < 4; i++) {           // B: 256 rows x 64B
            int f = tid + 256 * i, row = f >> 2, cc = (f & 3) * 16;
            cp16(base + row * ROWB + cc, Bp + (size_t)row * K6 + k0 + cc / 2);
        }
        asm volatile("cp.async.commit_group;" ::: "memory");
    };

    fetch(0); fetch(1);

    for (int c = 0; c < NCH; c++) {
        if (c + 1 < NCH) asm volatile("cp.async.wait_group 1;" ::: "memory");
        else             asm volatile("cp.async.wait_group 0;" ::: "memory");
        __syncthreads();
        if (c + 2 < NCH) fetch(c + 2);

        const int s = c - (c / 3) * 3;
        const uint32_t aB = smb + s * STAGE_B;
        const uint32_t bB = aB + 128 * ROWB;
        #pragma unroll
        for (int ks = 0; ks < 2; ks++) {
            const int kb = 2 * (ks * 16 + lcol);
            uint32_t afr[4][4];
            #pragma unroll
            for (int mi = 0; mi < 4; mi++)
                ldmx4(afr[mi], aB + (wm * 64 + mi * 16 + lrow) * ROWB + kb);
            #pragma unroll
            for (int nb = 0; nb < 4; nb++) {
                uint32_t bm[4];
                ldmx4(bm, bB + (wn * 64 + nb * 16 + lrow) * ROWB + kb);
                #pragma unroll
                for (int mi = 0; mi < 4; mi++) {
                    mma16816(acc[mi][2 * nb],     afr[mi], bm[0], bm[2]);
                    mma16816(acc[mi][2 * nb + 1], afr[mi], bm[1], bm[3]);
                }
            }
        }
    }

    // ---- epilogue: fragments -> g_hi/g_lo (bias + shift), bf16 hi/lo ----
    const size_t PSZ = (size_t)B_ * H_ * N_ * HD_;
    __nv_bfloat16* hip = g_hi + (size_t)z * PSZ;
    __nv_bfloat16* lop = g_lo + (size_t)z * PSZ;
    const int qrow = lane >> 2;
    const int qcol = (lane & 3) * 2;

    #pragma unroll
    for (int mi = 0; mi < 4; mi++) {
        #pragma unroll
        for (int hf = 0; hf < 2; hf++) {
            const int m  = m0 + wm * 64 + mi * 16 + qrow + hf * 8;
            const int b  = m >> 13;
            const int ns = m & (N_ - 1);
            #pragma unroll
            for (int ni = 0; ni < 8; ni++) {
                const int n = n0 + wn * 64 + ni * 8 + qcol;
                const int hh = n >> 7;
                const int d  = n & (HD_ - 1);
                const int nd = (hh < HALF_) ? ns : ((ns - SHIFT_) & (N_ - 1));
                const size_t off = (((size_t)b * H_ + hh) * N_ + nd) * HD_ + d;
                float v0 = acc[mi][ni][hf * 2 + 0] + bias[n];
                float v1 = acc[mi][ni][hf * 2 + 1] + bias[n + 1];
                __nv_bfloat16 h0 = __float2bfloat16(v0);
                __nv_bfloat16 h1 = __float2bfloat16(v1);
                __nv_bfloat16 e0 = __float2bfloat16(v0 - __bfloat162float(h0));
                __nv_bfloat16 e1 = __float2bfloat16(v1 - __bfloat162float(h1));
                *(__nv_bfloat162*)(hip + off) = __nv_bfloat162(h0, h1);
                *(__nv_bfloat162*)(lop + off) = __nv_bfloat162(e0, e1);
            }
        }
    }
}

// ---------------------------------------------------------------------------
// HMMA attention (proven R6): CTA per (qt, g, b*h). 256 threads = 8 warps.
// ---------------------------------------------------------------------------
#define OFF_RS  68608                 // 64*1072, fp32[64] row sums
#define OFF_Q   68864                 // bf16 [64][392]  (stride 784 B)
#define OFF_K   119040                // bf16 [64][392]
#define OFF_VH  119040                // reuse K region: bf16 [64][136] (stride 272 B)
#define OFF_VL  136448
#define AT_SMEM 169216

__global__ __launch_bounds__(256, 1) void attn_kernel(float* __restrict__ y)
{
    extern __shared__ char smc[];
    const int tid  = threadIdx.x;
    const int wid  = tid >> 5, lane = tid & 31;
    const int lrow = lane & 15, lcol = (lane >> 4) * 8;

    const int qt = blockIdx.x;               // 0..3
    const int g  = blockIdx.y;               // 0..31
    const int bh = blockIdx.z;
    const int b  = bh >> 4;
    const int h  = bh & 15;

    const size_t TOT   = (size_t)B_ * H_ * N_ * HD_;
    const size_t plane = ((size_t)b * H_ + h) * (size_t)N_ * HD_;
    const __nv_bfloat16* qh = g_hi + plane + (size_t)(g * GS_ + qt * 64) * HD_;
    const __nv_bfloat16* ql = g_lo + plane + (size_t)(g * GS_ + qt * 64) * HD_;
    const __nv_bfloat16* kh = g_hi + TOT     + plane + (size_t)(g * GS_) * HD_;
    const __nv_bfloat16* kl = g_lo + TOT     + plane + (size_t)(g * GS_) * HD_;
    const __nv_bfloat16* vh = g_hi + 2 * TOT + plane + (size_t)(g * GS_) * HD_;
    const __nv_bfloat16* vl = g_lo + 2 * TOT + plane + (size_t)(g * GS_) * HD_;

    // load Q: [Qh | Ql | Qh], 64 rows, stride 784 B
    #pragma unroll
    for (int i = 0; i < 4; i++) {
        int f = tid + 256 * i, r = f >> 4, c8 = (f & 15) * 8;
        uint4 hv = *(const uint4*)(qh + (size_t)r * HD_ + c8);
        uint4 lv = *(const uint4*)(ql + (size_t)r * HD_ + c8);
        char* rp = smc + OFF_Q + r * 784;
        *(uint4*)(rp + 2 * c8)         = hv;
        *(uint4*)(rp + 2 * (256 + c8)) = hv;
        *(uint4*)(rp + 2 * (128 + c8)) = lv;
    }

    // -------- phase A: scores --------
    const int wmA = wid & 3;      // 4 warps x 16 rows
    const int wnA = wid >> 2;     // 2 warps x 32 cols
    for (int kt = 0; kt <= qt; kt++) {
        __syncthreads();
        // load K chunk: [Kh | Kh | Kl]
        #pragma unroll
        for (int i = 0; i < 4; i++) {
            int f = tid + 256 * i, r = f >> 4, c8 = (f & 15) * 8;
            uint4 hv = *(const uint4*)(kh + (size_t)(kt * 64 + r) * HD_ + c8);
            uint4 lv = *(const uint4*)(kl + (size_t)(kt * 64 + r) * HD_ + c8);
            char* rp = smc + OFF_K + r * 784;
            *(uint4*)(rp + 2 * c8)         = hv;
            *(uint4*)(rp + 2 * (128 + c8)) = hv;
            *(uint4*)(rp + 2 * (256 + c8)) = lv;
        }
        __syncthreads();

        float accA[4][4];
        #pragma unroll
        for (int i = 0; i < 4; i++)
            #pragma unroll
            for (int j = 0; j < 4; j++) accA[i][j] = 0.f;

        #pragma unroll 4
        for (int ks = 0; ks < 24; ks++) {
            uint32_t afr[4];
            ldmx4(afr, s2u(smc + OFF_Q + (wmA * 16 + lrow) * 784 + 2 * (ks * 16 + lcol)));
            #pragma unroll
            for (int nb = 0; nb < 2; nb++) {
                uint32_t bm[4];
                ldmx4(bm, s2u(smc + OFF_K + (wnA * 32 + nb * 16 + lrow) * 784 + 2 * (ks * 16 + lcol)));
                mma16816(accA[nb * 2],     afr, bm[0], bm[2]);
                mma16816(accA[nb * 2 + 1], afr, bm[1], bm[3]);
            }
        }

        // mask + scale + store to S (fp32, union rows)
        const int qrow = wmA * 16 + (lane >> 2);
        const int qi0  = qt * 64 + qrow;
        const int qi1  = qi0 + 8;
        #pragma unroll
        for (int nt = 0; nt < 4; nt++) {
            int col = kt * 64 + wnA * 32 + nt * 8 + (lane & 3) * 2;
            float2 s0, s1;
            s0.x = (col     > qi0) ? NEGF : accA[nt][0] * SCALE_;
            s0.y = (col + 1 > qi0) ? NEGF : accA[nt][1] * SCALE_;
            s1.x = (col     > qi1) ? NEGF : accA[nt][2] * SCALE_;
            s1.y = (col + 1 > qi1) ? NEGF : accA[nt][3] * SCALE_;
            *(float2*)(smc + qrow * 1072 + 4 * col)       = s0;
            *(float2*)(smc + (qrow + 8) * 1072 + 4 * col) = s1;
        }
    }
    __syncthreads();

    // -------- phase B: softmax (unnormalized), write Ph/Pl bf16 --------
    {
        const int L  = (qt + 1) * 64;
        const int nv = L >> 5;               // 2,4,6,8
        for (int rr = 0; rr < 8; rr++) {
            const int r = wid * 8 + rr;
            float v[8];
            #pragma unroll
            for (int i = 0; i < 8; i++)
                if (i < nv) v[i] = *(const float*)(smc + r * 1072 + 4 * (lane + 32 * i));
            float m = -1e30f;
            #pragma unroll
            for (int i = 0; i < 8; i++) if (i < nv) m = fmaxf(m, v[i]);
            #pragma unroll
            for (int o = 16; o; o >>= 1) m = fmaxf(m, __shfl_xor_sync(~0u, m, o));
            float e[8];
            float sum = 0.f;
            #pragma unroll
            for (int i = 0; i < 8; i++)
                if (i < nv) { e[i] = __expf(v[i] - m); sum += e[i]; }
            __syncwarp();      // all S reads done before P overwrites the row
            #pragma unroll
            for (int i = 0; i < 8; i++)
                if (i < nv) {
                    __nv_bfloat16 ph = __float2bfloat16(e[i]);
                    __nv_bfloat16 pl = __float2bfloat16(e[i] - __bfloat162float(ph));
                    *(__nv_bfloat16*)(smc + r * 1072 + 2 * (lane + 32 * i))       = ph;
                    *(__nv_bfloat16*)(smc + r * 1072 + 512 + 2 * (lane + 32 * i)) = pl;
                }
            #pragma unroll
            for (int o = 16; o; o >>= 1) sum += __shfl_xor_sync(~0u, sum, o);
            if (lane == 0) *(float*)(smc + OFF_RS + 4 * r) = sum;
        }
    }
    __syncthreads();

    // -------- phase C: O = Ph Vh + Pl Vh + Ph Vl --------
    const int wmC = wid & 1;     // 2 warps x 32 rows
    const int wnC = wid >> 1;    // 4 warps x 32 d-cols
    float accC[2][4][4];
    #pragma unroll
    for (int a = 0; a < 2; a++)
        #pragma unroll
        for (int i = 0; i < 4; i++)
            #pragma unroll
            for (int j = 0; j < 4; j++) accC[a][i][j] = 0.f;

    for (int kt = 0; kt <= qt; kt++) {
        __syncthreads();
        #pragma unroll
        for (int i = 0; i < 4; i++) {
            int f = tid + 256 * i, r = f >> 4, c8 = (f & 15) * 8;
            *(uint4*)(smc + OFF_VH + r * 272 + 2 * c8) =
                *(const uint4*)(vh + (size_t)(kt * 64 + r) * HD_ + c8);
            *(uint4*)(smc + OFF_VL + r * 272 + 2 * c8) =
                *(const uint4*)(vl + (size_t)(kt * 64 + r) * HD_ + c8);
        }
        __syncthreads();

        #pragma unroll
        for (int pass = 0; pass < 3; pass++) {
            const int poff = (pass == 1) ? 512 : 0;        // Pl for pass 1
            const int voff = (pass == 2) ? OFF_VL : OFF_VH; // Vl for pass 2
            #pragma unroll
            for (int ks = 0; ks < 4; ks++) {
                uint32_t afr[2][4];
                #pragma unroll
                for (int mi = 0; mi < 2; mi++)
                    ldmx4(afr[mi], s2u(smc + (wmC * 32 + mi * 16 + lrow) * 1072 + poff
                                        + 2 * (kt * 64 + ks * 16 + lcol)));
                #pragma unroll
                for (int nb = 0; nb < 2; nb++) {
                    uint32_t bm[4];
                    ldmx4t(bm, s2u(smc + voff + (ks * 16 + lrow) * 272
                                    + 2 * (wnC * 32 + nb * 16 + lcol)));
                    #pragma unroll
                    for (int mi = 0; mi < 2; mi++) {
                        mma16816(accC[mi][nb * 2],     afr[mi], bm[0], bm[1]);
                        mma16816(accC[mi][nb * 2 + 1], afr[mi], bm[2], bm[3]);
                    }
                }
            }
        }
    }

    // epilogue: scale by 1/rowsum, unshift + head-interleave into y
    #pragma unroll
    for (int mi = 0; mi < 2; mi++) {
        const int row  = wmC * 32 + mi * 16 + (lane >> 2);
        const float i0 = 1.f / *(const float*)(smc + OFF_RS + 4 * row);
        const float i1 = 1.f / *(const float*)(smc + OFF_RS + 4 * (row + 8));
        const int np0 = g * GS_ + qt * 64 + row;
        const int np1 = np0 + 8;
        const int nf0 = (h < HALF_) ? np0 : ((np0 + SHIFT_) & (N_ - 1));
        const int nf1 = (h < HALF_) ? np1 : ((np1 + SHIFT_) & (N_ - 1));
        float* y0 = y + ((size_t)b * N_ + nf0) * C_ + h * HD_;
        float* y1 = y + ((size_t)b * N_ + nf1) * C_ + h * HD_;
        #pragma unroll
        for (int nt = 0; nt < 4; nt++) {
            const int d = wnC * 32 + nt * 8 + (lane & 3) * 2;
            *(float2*)(y0 + d) = make_float2(accC[mi][nt][0] * i0, accC[mi][nt][1] * i0);
            *(float2*)(y1 + d) = make_float2(accC[mi][nt][2] * i1, accC[mi][nt][3] * i1);
        }
    }
}

// ---------------------------------------------------------------------------
extern "C" void kernel_launch(void* const* d_in, const int* in_sizes, int n_in,
                              void* d_out, int out_size)
{
    const float* x  = (const float*)d_in[0];
    const float* Wq = (const float*)d_in[1];
    const float* bq = (const float*)d_in[2];
    const float* Wk = (const float*)d_in[3];
    const float* bk = (const float*)d_in[4];
    const float* Wv = (const float*)d_in[5];
    const float* bv = (const float*)d_in[6];
    float* y = (float*)d_out;

    __nv_bfloat16 *Ag, *Bg;
    cudaGetSymbolAddress((void**)&Ag, g_A);
    cudaGetSymbolAddress((void**)&Bg, g_B);

    // hi/lo splits: A = [hi|lo|hi], B = [hi|hi|lo]
    split_kernel<<<MROWS * 2, 256>>>(x,  Ag, 2 * C_, C_);
    split_kernel<<<C_ * 2,    256>>>(Wq, Bg + (size_t)0 * C_ * K6, C_, 2 * C_);
    split_kernel<<<C_ * 2,    256>>>(Wk, Bg + (size_t)1 * C_ * K6, C_, 2 * C_);
    split_kernel<<<C_ * 2,    256>>>(Wv, Bg + (size_t)2 * C_ * K6, C_, 2 * C_);

    // HMMA projections v2 (cp.async pipeline, fused bias + shift, hi/lo out)
    cudaFuncSetAttribute(gemm_kernel,
                         cudaFuncAttributeMaxDynamicSharedMemorySize, GM_SMEM);
    gemm_kernel<<<dim3(C_ / 256, MROWS / 128, 3), 256, GM_SMEM>>>(bq, bk, bv);

    // HMMA attention
    cudaFuncSetAttribute(attn_kernel,
                         cudaFuncAttributeMaxDynamicSharedMemorySize, AT_SMEM);
    attn_kernel<<<dim3(4, G_, B_ * H_), 256, AT_SMEM>>>(y);
}

// round 8
// speedup vs baseline: 1.1330x; 1.1330x over previous
#include <cuda_runtime.h>
#include <cuda_bf16.h>
#include <math.h>
#include <stdint.h>

// ---------------------------------------------------------------------------
// Problem constants
// ---------------------------------------------------------------------------
#define B_    2
#define N_    8192
#define C_    2048
#define H_    16
#define HD_   128
#define GS_   256
#define G_    (N_/GS_)     // 32
#define HALF_ 8
#define SHIFT_ 128
#define SCALE_ 0.08838834764831843f   // 1/sqrt(128)
#define NEGF  -1e9f

#define MROWS (B_*N_)      // 16384
#define K6    (3*C_)       // 6144 augmented K: [hi|lo|hi] x [hi|hi|lo]

// scratch
__device__ __nv_bfloat16 g_A[(size_t)MROWS * K6];            // x_aug  [16384][6144]
__device__ __nv_bfloat16 g_B[(size_t)3 * C_ * K6];           // W_aug  [3][2048][6144]
__device__ __nv_bfloat16 g_hi[(size_t)3 * B_ * H_ * N_ * HD_];  // qkv hi (shifted)
__device__ __nv_bfloat16 g_lo[(size_t)3 * B_ * H_ * N_ * HD_];  // qkv lo (shifted)

// ---------------------------------------------------------------------------
// split: fp32 [rows][2048] -> bf16 [rows][6144]; hi at col 0 and hi2_off, lo at lo_off
// ---------------------------------------------------------------------------
__global__ __launch_bounds__(256) void split_kernel(
    const float* __restrict__ in, __nv_bfloat16* __restrict__ out,
    int hi2_off, int lo_off)
{
    size_t idx = (size_t)blockIdx.x * 256 + threadIdx.x;   // one float4 each
    float4 v = ((const float4*)in)[idx];
    size_t m  = idx >> 9;          // 512 float4 per row
    int    c  = (int)(idx & 511) * 4;

    __nv_bfloat16 h0 = __float2bfloat16(v.x);
    __nv_bfloat16 h1 = __float2bfloat16(v.y);
    __nv_bfloat16 h2 = __float2bfloat16(v.z);
    __nv_bfloat16 h3 = __float2bfloat16(v.w);
    __nv_bfloat16 l0 = __float2bfloat16(v.x - __bfloat162float(h0));
    __nv_bfloat16 l1 = __float2bfloat16(v.y - __bfloat162float(h1));
    __nv_bfloat16 l2 = __float2bfloat16(v.z - __bfloat162float(h2));
    __nv_bfloat16 l3 = __float2bfloat16(v.w - __bfloat162float(h3));

    __nv_bfloat162 hA(h0, h1), hB(h2, h3), lA(l0, l1), lB(l2, l3);
    __nv_bfloat16* rowp = out + m * K6;
    *(__nv_bfloat162*)(rowp + c)               = hA;
    *(__nv_bfloat162*)(rowp + c + 2)           = hB;
    *(__nv_bfloat162*)(rowp + hi2_off + c)     = hA;
    *(__nv_bfloat162*)(rowp + hi2_off + c + 2) = hB;
    *(__nv_bfloat162*)(rowp + lo_off + c)      = lA;
    *(__nv_bfloat162*)(rowp + lo_off + c + 2)  = lB;
}

// ---------------------------------------------------------------------------
// common MMA helpers (proven R5/R6)
// ---------------------------------------------------------------------------
__device__ __forceinline__ uint32_t s2u(const void* p) {
    uint32_t a;
    asm("{ .reg .u64 t; cvta.to.shared.u64 t, %1; cvt.u32.u64 %0, t; }"
        : "=r"(a) : "l"(p));
    return a;
}
__device__ __forceinline__ void ldmx4(uint32_t* r, uint32_t addr) {
    asm volatile("ldmatrix.sync.aligned.m8n8.x4.shared.b16 {%0,%1,%2,%3}, [%4];"
                 : "=r"(r[0]), "=r"(r[1]), "=r"(r[2]), "=r"(r[3]) : "r"(addr));
}
__device__ __forceinline__ void ldmx4t(uint32_t* r, uint32_t addr) {
    asm volatile("ldmatrix.sync.aligned.m8n8.x4.trans.shared.b16 {%0,%1,%2,%3}, [%4];"
                 : "=r"(r[0]), "=r"(r[1]), "=r"(r[2]), "=r"(r[3]) : "r"(addr));
}
__device__ __forceinline__ void mma16816(float* c, const uint32_t* a,
                                         uint32_t b0, uint32_t b1) {
    asm volatile(
        "mma.sync.aligned.m16n8k16.row.col.f32.bf16.bf16.f32 "
        "{%0,%1,%2,%3}, {%4,%5,%6,%7}, {%8,%9}, {%0,%1,%2,%3};"
        : "+f"(c[0]), "+f"(c[1]), "+f"(c[2]), "+f"(c[3])
        : "r"(a[0]), "r"(a[1]), "r"(a[2]), "r"(a[3]), "r"(b0), "r"(b1));
}
__device__ __forceinline__ void cp16(uint32_t dst, const void* src) {
    asm volatile("cp.async.cg.shared.global [%0], [%1], 16;"
                 :: "r"(dst), "l"(src) : "memory");
}

// ---------------------------------------------------------------------------
// HMMA GEMM v3: R5 geometry (tile 128x128, warp 32x64, 2 CTAs/SM) with
// cp.async 3-stage pipeline, ONE sync per chunk. Epilogue -> bf16 hi/lo qkv.
// ---------------------------------------------------------------------------
#define KC      32
#define NCH     (K6/KC)        // 192
#define GROWB   80             // 32 bf16 + 8 pad
#define GSTAGE  (256*GROWB)    // A(128 rows) + B(128 rows) = 20480 B
#define GM_SMEM (3*GSTAGE)     // 61440 B -> 2 CTAs/SM

__global__ __launch_bounds__(256, 2) void gemm_kernel(
    const float* __restrict__ bq, const float* __restrict__ bk,
    const float* __restrict__ bv)
{
    extern __shared__ char smg[];
    const uint32_t smb = s2u(smg);

    const int tid  = threadIdx.x;
    const int wid  = tid >> 5, lane = tid & 31;
    const int wm   = wid & 3;          // 4 warp rows x 32
    const int wn   = wid >> 2;         // 2 warp cols x 64
    const int lrow = lane & 15;
    const int lcol = (lane >> 4) * 8;

    const int n0 = blockIdx.x * 128;
    const int m0 = blockIdx.y * 128;
    const int z  = blockIdx.z;
    const __nv_bfloat16* __restrict__ Ap = g_A + (size_t)m0 * K6;
    const __nv_bfloat16* __restrict__ Bp = g_B + (size_t)z * C_ * K6 + (size_t)n0 * K6;
    const float* __restrict__ bias = (z == 0) ? bq : (z == 1) ? bk : bv;

    float acc[2][8][4];
    #pragma unroll
    for (int i = 0; i < 2; i++)
        #pragma unroll
        for (int j = 0; j < 8; j++)
            #pragma unroll
            for (int k = 0; k < 4; k++) acc[i][j][k] = 0.f;

    auto fetch = [&](int c) {
        const int s = c - (c / 3) * 3;
        const size_t k0 = (size_t)c * KC;
        const uint32_t base = smb + s * GSTAGE;
        #pragma unroll
        for (int i = 0; i < 2; i++) {            // A: 128 rows x 64 B
            int f = tid + 256 * i, row = f >> 2, cc = (f & 3) * 16;
            cp16(base + row * GROWB + cc, Ap + (size_t)row * K6 + k0 + cc / 2);
        }
        #pragma unroll
        for (int i = 0; i < 2; i++) {            // B: 128 rows x 64 B
            int f = tid + 256 * i, row = f >> 2, cc = (f & 3) * 16;
            cp16(base + 128 * GROWB + row * GROWB + cc,
                 Bp + (size_t)row * K6 + k0 + cc / 2);
        }
        asm volatile("cp.async.commit_group;" ::: "memory");
    };

    fetch(0); fetch(1);

    for (int c = 0; c < NCH; c++) {
        if (c + 1 < NCH) asm volatile("cp.async.wait_group 1;" ::: "memory");
        else             asm volatile("cp.async.wait_group 0;" ::: "memory");
        __syncthreads();
        if (c + 2 < NCH) fetch(c + 2);

        const int s = c - (c / 3) * 3;
        const uint32_t aB = smb + s * GSTAGE;
        const uint32_t bB = aB + 128 * GROWB;
        #pragma unroll
        for (int ks = 0; ks < 2; ks++) {
            const int kb = 2 * (ks * 16 + lcol);
            uint32_t afr[2][4];
            #pragma unroll
            for (int mi = 0; mi < 2; mi++)
                ldmx4(afr[mi], aB + (wm * 32 + mi * 16 + lrow) * GROWB + kb);
            #pragma unroll
            for (int nb = 0; nb < 4; nb++) {
                uint32_t bm[4];
                ldmx4(bm, bB + (wn * 64 + nb * 16 + lrow) * GROWB + kb);
                #pragma unroll
                for (int mi = 0; mi < 2; mi++) {
                    mma16816(acc[mi][2 * nb],     afr[mi], bm[0], bm[2]);
                    mma16816(acc[mi][2 * nb + 1], afr[mi], bm[1], bm[3]);
                }
            }
        }
    }

    // epilogue: fragments -> g_hi/g_lo (bias + shift), bf16 hi/lo
    const size_t PSZ = (size_t)B_ * H_ * N_ * HD_;
    __nv_bfloat16* hip = g_hi + (size_t)z * PSZ;
    __nv_bfloat16* lop = g_lo + (size_t)z * PSZ;
    const int qrow = lane >> 2;
    const int qcol = (lane & 3) * 2;

    #pragma unroll
    for (int mi = 0; mi < 2; mi++) {
        #pragma unroll
        for (int hf = 0; hf < 2; hf++) {
            const int m  = m0 + wm * 32 + mi * 16 + qrow + hf * 8;
            const int b  = m >> 13;
            const int ns = m & (N_ - 1);
            #pragma unroll
            for (int ni = 0; ni < 8; ni++) {
                const int n = n0 + wn * 64 + ni * 8 + qcol;
                const int hh = n >> 7;
                const int d  = n & (HD_ - 1);
                const int nd = (hh < HALF_) ? ns : ((ns - SHIFT_) & (N_ - 1));
                const size_t off = (((size_t)b * H_ + hh) * N_ + nd) * HD_ + d;
                float v0 = acc[mi][ni][hf * 2 + 0] + bias[n];
                float v1 = acc[mi][ni][hf * 2 + 1] + bias[n + 1];
                __nv_bfloat16 h0 = __float2bfloat16(v0);
                __nv_bfloat16 h1 = __float2bfloat16(v1);
                __nv_bfloat16 e0 = __float2bfloat16(v0 - __bfloat162float(h0));
                __nv_bfloat16 e1 = __float2bfloat16(v1 - __bfloat162float(h1));
                *(__nv_bfloat162*)(hip + off) = __nv_bfloat162(h0, h1);
                *(__nv_bfloat162*)(lop + off) = __nv_bfloat162(e0, e1);
            }
        }
    }
}

// ---------------------------------------------------------------------------
// FA2-style HMMA attention: CTA = (qt, g, b*h), 128 threads, 4 warps x 16 rows.
// S in registers, online softmax, P re-packed C-frag -> A-frag (hi/lo).
// smem: Q [64][264 bf16] (hi|lo), K [64][264], Vh [64][136], Vl [64][136]
// ---------------------------------------------------------------------------
#define AQ_STR  528              // bytes per Q/K row (256 bf16 + 8 pad)
#define AV_STR  272              // bytes per V row (128 bf16 + 8 pad)
#define OFF_AK  33792            // 64*528
#define OFF_AVH 67584
#define OFF_AVL 84992
#define AT_SMEM 102400           // -> 2 CTAs/SM

__global__ __launch_bounds__(128, 2) void attn_kernel(float* __restrict__ y)
{
    extern __shared__ char smc[];
    const uint32_t smb = s2u(smc);
    const int tid  = threadIdx.x;
    const int w    = tid >> 5, lane = tid & 31;
    const int lrow = lane & 15, lcol = (lane >> 4) * 8;

    const int qt = blockIdx.x;               // 0..3
    const int g  = blockIdx.y;               // 0..31
    const int bh = blockIdx.z;
    const int b  = bh >> 4;
    const int h  = bh & 15;

    const size_t TOT   = (size_t)B_ * H_ * N_ * HD_;
    const size_t plane = ((size_t)b * H_ + h) * (size_t)N_ * HD_;
    const __nv_bfloat16* qh = g_hi + plane + (size_t)(g * GS_ + qt * 64) * HD_;
    const __nv_bfloat16* ql = g_lo + plane + (size_t)(g * GS_ + qt * 64) * HD_;
    const __nv_bfloat16* kh = g_hi + TOT     + plane + (size_t)(g * GS_) * HD_;
    const __nv_bfloat16* kl = g_lo + TOT     + plane + (size_t)(g * GS_) * HD_;
    const __nv_bfloat16* vh = g_hi + 2 * TOT + plane + (size_t)(g * GS_) * HD_;
    const __nv_bfloat16* vl = g_lo + 2 * TOT + plane + (size_t)(g * GS_) * HD_;

    // load Q tile: [Qh | Ql], 64 rows x 528 B
    #pragma unroll
    for (int i = 0; i < 8; i++) {
        int f = tid + 128 * i, r = f >> 4, c8 = (f & 15) * 8;
        *(uint4*)(smc + r * AQ_STR + 2 * c8) =
            *(const uint4*)(qh + (size_t)r * HD_ + c8);
        *(uint4*)(smc + r * AQ_STR + 256 + 2 * c8) =
            *(const uint4*)(ql + (size_t)r * HD_ + c8);
    }

    float m0 = -1e30f, m1 = -1e30f, l0 = 0.f, l1 = 0.f;
    float accO[16][4];
    #pragma unroll
    for (int i = 0; i < 16; i++)
        #pragma unroll
        for (int j = 0; j < 4; j++) accO[i][j] = 0.f;

    for (int kt = 0; kt <= qt; kt++) {
        __syncthreads();     // prev V reads done / Q store visible (first iter)
        #pragma unroll
        for (int i = 0; i < 8; i++) {
            int f = tid + 128 * i, r = f >> 4, c8 = (f & 15) * 8;
            const size_t go = (size_t)(kt * 64 + r) * HD_ + c8;
            *(uint4*)(smc + OFF_AK + r * AQ_STR + 2 * c8)        = *(const uint4*)(kh + go);
            *(uint4*)(smc + OFF_AK + r * AQ_STR + 256 + 2 * c8)  = *(const uint4*)(kl + go);
            *(uint4*)(smc + OFF_AVH + r * AV_STR + 2 * c8)       = *(const uint4*)(vh + go);
            *(uint4*)(smc + OFF_AVL + r * AV_STR + 2 * c8)       = *(const uint4*)(vl + go);
        }
        __syncthreads();

        // ---- S = Qaug . Kaug^T  (3 passes, k=128 each) ----
        float s[8][4];
        #pragma unroll
        for (int i = 0; i < 8; i++)
            #pragma unroll
            for (int j = 0; j < 4; j++) s[i][j] = 0.f;

        #pragma unroll
        for (int pass = 0; pass < 3; pass++) {
            const int qoff = (pass == 1) ? 256 : 0;    // bytes: Ql at +256
            const int koff = (pass == 2) ? 256 : 0;    // bytes: Kl at +256
            #pragma unroll
            for (int ks = 0; ks < 8; ks++) {
                uint32_t afr[4];
                ldmx4(afr, smb + (w * 16 + lrow) * AQ_STR + qoff + 2 * (ks * 16 + lcol));
                #pragma unroll
                for (int nb = 0; nb < 4; nb++) {
                    uint32_t bm[4];
                    ldmx4(bm, smb + OFF_AK + (nb * 16 + lrow) * AQ_STR + koff
                               + 2 * (ks * 16 + lcol));
                    mma16816(s[nb * 2],     afr, bm[0], bm[2]);
                    mma16816(s[nb * 2 + 1], afr, bm[1], bm[3]);
                }
            }
        }

        // ---- scale + causal mask (diagonal tile only) ----
        #pragma unroll
        for (int nt = 0; nt < 8; nt++)
            #pragma unroll
            for (int j = 0; j < 4; j++) s[nt][j] *= SCALE_;
        if (kt == qt) {
            const int r0 = w * 16 + (lane >> 2);
            const int r1 = r0 + 8;
            #pragma unroll
            for (int nt = 0; nt < 8; nt++) {
                const int col = nt * 8 + (lane & 3) * 2;
                if (col     > r0) s[nt][0] = NEGF;
                if (col + 1 > r0) s[nt][1] = NEGF;
                if (col     > r1) s[nt][2] = NEGF;
                if (col + 1 > r1) s[nt][3] = NEGF;
            }
        }

        // ---- online softmax (rows r0, r1) ----
        float tm0 = -1e30f, tm1 = -1e30f;
        #pragma unroll
        for (int nt = 0; nt < 8; nt++) {
            tm0 = fmaxf(tm0, fmaxf(s[nt][0], s[nt][1]));
            tm1 = fmaxf(tm1, fmaxf(s[nt][2], s[nt][3]));
        }
        tm0 = fmaxf(tm0, __shfl_xor_sync(~0u, tm0, 1));
        tm0 = fmaxf(tm0, __shfl_xor_sync(~0u, tm0, 2));
        tm1 = fmaxf(tm1, __shfl_xor_sync(~0u, tm1, 1));
        tm1 = fmaxf(tm1, __shfl_xor_sync(~0u, tm1, 2));

        const float mn0 = fmaxf(m0, tm0), mn1 = fmaxf(m1, tm1);
        const float a0 = __expf(m0 - mn0), a1 = __expf(m1 - mn1);
        float rs0 = 0.f, rs1 = 0.f;
        #pragma unroll
        for (int nt = 0; nt < 8; nt++) {
            s[nt][0] = __expf(s[nt][0] - mn0); rs0 += s[nt][0];
            s[nt][1] = __expf(s[nt][1] - mn0); rs0 += s[nt][1];
            s[nt][2] = __expf(s[nt][2] - mn1); rs1 += s[nt][2];
            s[nt][3] = __expf(s[nt][3] - mn1); rs1 += s[nt][3];
        }
        rs0 += __shfl_xor_sync(~0u, rs0, 1); rs0 += __shfl_xor_sync(~0u, rs0, 2);
        rs1 += __shfl_xor_sync(~0u, rs1, 1); rs1 += __shfl_xor_sync(~0u, rs1, 2);
        l0 = l0 * a0 + rs0;  l1 = l1 * a1 + rs1;
        m0 = mn0;            m1 = mn1;
        #pragma unroll
        for (int dt = 0; dt < 16; dt++) {
            accO[dt][0] *= a0; accO[dt][1] *= a0;
            accO[dt][2] *= a1; accO[dt][3] *= a1;
        }

        // ---- P (C-frag -> A-frag, hi/lo) . V ----
        #pragma unroll
        for (int kk = 0; kk < 4; kk++) {
            uint32_t ph[4], pl[4];
            auto mk = [&](float p0, float p1, uint32_t& hh, uint32_t& ll) {
                __nv_bfloat16 c0 = __float2bfloat16(p0);
                __nv_bfloat16 c1 = __float2bfloat16(p1);
                __nv_bfloat162 hv(c0, c1);
                hh = *(uint32_t*)&hv;
                __nv_bfloat162 lv(__float2bfloat16(p0 - __bfloat162float(c0)),
                                  __float2bfloat16(p1 - __bfloat162float(c1)));
                ll = *(uint32_t*)&lv;
            };
            mk(s[2 * kk][0],     s[2 * kk][1],     ph[0], pl[0]);
            mk(s[2 * kk][2],     s[2 * kk][3],     ph[1], pl[1]);
            mk(s[2 * kk + 1][0], s[2 * kk + 1][1], ph[2], pl[2]);
            mk(s[2 * kk + 1][2], s[2 * kk + 1][3], ph[3], pl[3]);
            #pragma unroll
            for (int dt = 0; dt < 8; dt++) {
                uint32_t bm[4];
                ldmx4t(bm, smb + OFF_AVH + (kk * 16 + lrow) * AV_STR
                            + 2 * (dt * 16 + lcol));
                mma16816(accO[dt * 2],     ph, bm[0], bm[1]);
                mma16816(accO[dt * 2 + 1], ph, bm[2], bm[3]);
                mma16816(accO[dt * 2],     pl, bm[0], bm[1]);
                mma16816(accO[dt * 2 + 1], pl, bm[2], bm[3]);
                ldmx4t(bm, smb + OFF_AVL + (kk * 16 + lrow) * AV_STR
                            + 2 * (dt * 16 + lcol));
                mma16816(accO[dt * 2],     ph, bm[0], bm[1]);
                mma16816(accO[dt * 2 + 1], ph, bm[2], bm[3]);
            }
        }
    }

    // ---- epilogue: normalize, unshift + head-interleave into y ----
    const float i0 = 1.f / l0, i1 = 1.f / l1;
    const int row = w * 16 + (lane >> 2);
    const int np0 = g * GS_ + qt * 64 + row;
    const int np1 = np0 + 8;
    const int nf0 = (h < HALF_) ? np0 : ((np0 + SHIFT_) & (N_ - 1));
    const int nf1 = (h < HALF_) ? np1 : ((np1 + SHIFT_) & (N_ - 1));
    float* y0 = y + ((size_t)b * N_ + nf0) * C_ + h * HD_;
    float* y1 = y + ((size_t)b * N_ + nf1) * C_ + h * HD_;
    #pragma unroll
    for (int dt = 0; dt < 16; dt++) {
        const int d = dt * 8 + (lane & 3) * 2;
        *(float2*)(y0 + d) = make_float2(accO[dt][0] * i0, accO[dt][1] * i0);
        *(float2*)(y1 + d) = make_float2(accO[dt][2] * i1, accO[dt][3] * i1);
    }
}

// ---------------------------------------------------------------------------
extern "C" void kernel_launch(void* const* d_in, const int* in_sizes, int n_in,
                              void* d_out, int out_size)
{
    const float* x  = (const float*)d_in[0];
    const float* Wq = (const float*)d_in[1];
    const float* bq = (const float*)d_in[2];
    const float* Wk = (const float*)d_in[3];
    const float* bk = (const float*)d_in[4];
    const float* Wv = (const float*)d_in[5];
    const float* bv = (const float*)d_in[6];
    float* y = (float*)d_out;

    __nv_bfloat16 *Ag, *Bg;
    cudaGetSymbolAddress((void**)&Ag, g_A);
    cudaGetSymbolAddress((void**)&Bg, g_B);

    // hi/lo splits: A = [hi|lo|hi], B = [hi|hi|lo]
    split_kernel<<<MROWS * 2, 256>>>(x,  Ag, 2 * C_, C_);
    split_kernel<<<C_ * 2,    256>>>(Wq, Bg + (size_t)0 * C_ * K6, C_, 2 * C_);
    split_kernel<<<C_ * 2,    256>>>(Wk, Bg + (size_t)1 * C_ * K6, C_, 2 * C_);
    split_kernel<<<C_ * 2,    256>>>(Wv, Bg + (size_t)2 * C_ * K6, C_, 2 * C_);

    // HMMA projections v3 (128x128, 2 CTA/SM, cp.async, 1 sync/chunk)
    cudaFuncSetAttribute(gemm_kernel,
                         cudaFuncAttributeMaxDynamicSharedMemorySize, GM_SMEM);
    gemm_kernel<<<dim3(C_ / 128, MROWS / 128, 3), 256, GM_SMEM>>>(bq, bk, bv);

    // FA2-style attention
    cudaFuncSetAttribute(attn_kernel,
                         cudaFuncAttributeMaxDynamicSharedMemorySize, AT_SMEM);
    attn_kernel<<<dim3(4, G_, B_ * H_), 128, AT_SMEM>>>(y);
}

// round 10
// speedup vs baseline: 1.2986x; 1.1462x over previous
#include <cuda_runtime.h>
#include <cuda_bf16.h>
#include <math.h>
#include <stdint.h>

// ---------------------------------------------------------------------------
// Problem constants
// ---------------------------------------------------------------------------
#define B_    2
#define N_    8192
#define C_    2048
#define H_    16
#define HD_   128
#define GS_   256
#define G_    (N_/GS_)     // 32
#define HALF_ 8
#define SHIFT_ 128
#define SCALE_ 0.08838834764831843f   // 1/sqrt(128)
#define NEGF  -1e9f

#define MROWS (B_*N_)      // 16384
#define K6    (3*C_)       // 6144 augmented K: [hi|lo|hi] x [hi|hi|lo]

// scratch
__device__ __nv_bfloat16 g_A[(size_t)MROWS * K6];            // x_aug  [16384][6144]
__device__ __nv_bfloat16 g_B[(size_t)3 * C_ * K6];           // W_aug  [3][2048][6144]
__device__ __nv_bfloat16 g_hi[(size_t)3 * B_ * H_ * N_ * HD_];  // qkv hi (shifted)
__device__ __nv_bfloat16 g_lo[(size_t)3 * B_ * H_ * N_ * HD_];  // qkv lo (shifted)

// ---------------------------------------------------------------------------
// split: fp32 [rows][2048] -> bf16 [rows][6144]; hi at col 0 and hi2_off, lo at lo_off
// ---------------------------------------------------------------------------
__global__ __launch_bounds__(256) void split_kernel(
    const float* __restrict__ in, __nv_bfloat16* __restrict__ out,
    int hi2_off, int lo_off)
{
    size_t idx = (size_t)blockIdx.x * 256 + threadIdx.x;   // one float4 each
    float4 v = ((const float4*)in)[idx];
    size_t m  = idx >> 9;          // 512 float4 per row
    int    c  = (int)(idx & 511) * 4;

    __nv_bfloat16 h0 = __float2bfloat16(v.x);
    __nv_bfloat16 h1 = __float2bfloat16(v.y);
    __nv_bfloat16 h2 = __float2bfloat16(v.z);
    __nv_bfloat16 h3 = __float2bfloat16(v.w);
    __nv_bfloat16 l0 = __float2bfloat16(v.x - __bfloat162float(h0));
    __nv_bfloat16 l1 = __float2bfloat16(v.y - __bfloat162float(h1));
    __nv_bfloat16 l2 = __float2bfloat16(v.z - __bfloat162float(h2));
    __nv_bfloat16 l3 = __float2bfloat16(v.w - __bfloat162float(h3));

    __nv_bfloat162 hA(h0, h1), hB(h2, h3), lA(l0, l1), lB(l2, l3);
    __nv_bfloat16* rowp = out + m * K6;
    *(__nv_bfloat162*)(rowp + c)               = hA;
    *(__nv_bfloat162*)(rowp + c + 2)           = hB;
    *(__nv_bfloat162*)(rowp + hi2_off + c)     = hA;
    *(__nv_bfloat162*)(rowp + hi2_off + c + 2) = hB;
    *(__nv_bfloat162*)(rowp + lo_off + c)      = lA;
    *(__nv_bfloat162*)(rowp + lo_off + c + 2)  = lB;
}

// ---------------------------------------------------------------------------
// common MMA helpers (proven R5-R8)
// ---------------------------------------------------------------------------
__device__ __forceinline__ uint32_t s2u(const void* p) {
    uint32_t a;
    asm("{ .reg .u64 t; cvta.to.shared.u64 t, %1; cvt.u32.u64 %0, t; }"
        : "=r"(a) : "l"(p));
    return a;
}
__device__ __forceinline__ void ldmx4(uint32_t* r, uint32_t addr) {
    asm volatile("ldmatrix.sync.aligned.m8n8.x4.shared.b16 {%0,%1,%2,%3}, [%4];"
                 : "=r"(r[0]), "=r"(r[1]), "=r"(r[2]), "=r"(r[3]) : "r"(addr));
}
__device__ __forceinline__ void ldmx4t(uint32_t* r, uint32_t addr) {
    asm volatile("ldmatrix.sync.aligned.m8n8.x4.trans.shared.b16 {%0,%1,%2,%3}, [%4];"
                 : "=r"(r[0]), "=r"(r[1]), "=r"(r[2]), "=r"(r[3]) : "r"(addr));
}
__device__ __forceinline__ void mma16816(float* c, const uint32_t* a,
                                         uint32_t b0, uint32_t b1) {
    asm volatile(
        "mma.sync.aligned.m16n8k16.row.col.f32.bf16.bf16.f32 "
        "{%0,%1,%2,%3}, {%4,%5,%6,%7}, {%8,%9}, {%0,%1,%2,%3};"
        : "+f"(c[0]), "+f"(c[1]), "+f"(c[2]), "+f"(c[3])
        : "r"(a[0]), "r"(a[1]), "r"(a[2]), "r"(a[3]), "r"(b0), "r"(b1));
}
__device__ __forceinline__ void cp16(uint32_t dst, const void* src) {
    asm volatile("cp.async.cg.shared.global [%0], [%1], 16;"
                 :: "r"(dst), "l"(src) : "memory");
}

// ---------------------------------------------------------------------------
// HMMA GEMM v4b: tile 128x128, warp 32x64, KC=64, 3-stage cp.async, 2 CTAs/SM
// GROWB=144 (multiple of 16 -> legal cp.async dst; banks 4r mod 32 -> no conflict)
// ---------------------------------------------------------------------------
#define KC      64
#define NCH     (K6/KC)        // 96
#define GROWB   144            // 64 bf16 (128 B) + 16 pad (16B-aligned rows!)
#define GSTAGE  (256*GROWB)    // A(128 rows) + B(128 rows) = 36864 B
#define GM_SMEM (3*GSTAGE)     // 110592 B -> 2 CTAs/SM (216 KB of 228 KB)

__global__ __launch_bounds__(256, 2) void gemm_kernel(
    const float* __restrict__ bq, const float* __restrict__ bk,
    const float* __restrict__ bv)
{
    extern __shared__ char smg[];
    const uint32_t smb = s2u(smg);

    const int tid  = threadIdx.x;
    const int wid  = tid >> 5, lane = tid & 31;
    const int wm   = wid & 3;          // 4 warp rows x 32
    const int wn   = wid >> 2;         // 2 warp cols x 64
    const int lrow = lane & 15;
    const int lcol = (lane >> 4) * 8;

    const int n0 = blockIdx.x * 128;
    const int m0 = blockIdx.y * 128;
    const int z  = blockIdx.z;
    const __nv_bfloat16* __restrict__ Ap = g_A + (size_t)m0 * K6;
    const __nv_bfloat16* __restrict__ Bp = g_B + (size_t)z * C_ * K6 + (size_t)n0 * K6;
    const float* __restrict__ bias = (z == 0) ? bq : (z == 1) ? bk : bv;

    float acc[2][8][4];
    #pragma unroll
    for (int i = 0; i < 2; i++)
        #pragma unroll
        for (int j = 0; j < 8; j++)
            #pragma unroll
            for (int k = 0; k < 4; k++) acc[i][j][k] = 0.f;

    auto fetch = [&](int c) {
        const int s = c - (c / 3) * 3;
        const size_t k0 = (size_t)c * KC;
        const uint32_t base = smb + s * GSTAGE;
        #pragma unroll
        for (int i = 0; i < 4; i++) {            // A: 128 rows x 128 B
            int f = tid + 256 * i, row = f >> 3, cc = (f & 7) * 16;
            cp16(base + row * GROWB + cc, Ap + (size_t)row * K6 + k0 + cc / 2);
        }
        #pragma unroll
        for (int i = 0; i < 4; i++) {            // B: 128 rows x 128 B
            int f = tid + 256 * i, row = f >> 3, cc = (f & 7) * 16;
            cp16(base + 128 * GROWB + row * GROWB + cc,
                 Bp + (size_t)row * K6 + k0 + cc / 2);
        }
        asm volatile("cp.async.commit_group;" ::: "memory");
    };

    fetch(0); fetch(1);

    for (int c = 0; c < NCH; c++) {
        if (c + 1 < NCH) asm volatile("cp.async.wait_group 1;" ::: "memory");
        else             asm volatile("cp.async.wait_group 0;" ::: "memory");
        __syncthreads();
        if (c + 2 < NCH) fetch(c + 2);

        const int s = c - (c / 3) * 3;
        const uint32_t aB = smb + s * GSTAGE;
        const uint32_t bB = aB + 128 * GROWB;
        #pragma unroll
        for (int ks = 0; ks < 4; ks++) {
            const int kb = 2 * (ks * 16 + lcol);
            uint32_t afr[2][4];
            #pragma unroll
            for (int mi = 0; mi < 2; mi++)
                ldmx4(afr[mi], aB + (wm * 32 + mi * 16 + lrow) * GROWB + kb);
            #pragma unroll
            for (int nb = 0; nb < 4; nb++) {
                uint32_t bm[4];
                ldmx4(bm, bB + (wn * 64 + nb * 16 + lrow) * GROWB + kb);
                #pragma unroll
                for (int mi = 0; mi < 2; mi++) {
                    mma16816(acc[mi][2 * nb],     afr[mi], bm[0], bm[2]);
                    mma16816(acc[mi][2 * nb + 1], afr[mi], bm[1], bm[3]);
                }
            }
        }
    }

    // epilogue: fragments -> g_hi/g_lo (bias + shift), bf16 hi/lo
    const size_t PSZ = (size_t)B_ * H_ * N_ * HD_;
    __nv_bfloat16* hip = g_hi + (size_t)z * PSZ;
    __nv_bfloat16* lop = g_lo + (size_t)z * PSZ;
    const int qrow = lane >> 2;
    const int qcol = (lane & 3) * 2;

    #pragma unroll
    for (int mi = 0; mi < 2; mi++) {
        #pragma unroll
        for (int hf = 0; hf < 2; hf++) {
            const int m  = m0 + wm * 32 + mi * 16 + qrow + hf * 8;
            const int b  = m >> 13;
            const int ns = m & (N_ - 1);
            #pragma unroll
            for (int ni = 0; ni < 8; ni++) {
                const int n = n0 + wn * 64 + ni * 8 + qcol;
                const int hh = n >> 7;
                const int d  = n & (HD_ - 1);
                const int nd = (hh < HALF_) ? ns : ((ns - SHIFT_) & (N_ - 1));
                const size_t off = (((size_t)b * H_ + hh) * N_ + nd) * HD_ + d;
                float v0 = acc[mi][ni][hf * 2 + 0] + bias[n];
                float v1 = acc[mi][ni][hf * 2 + 1] + bias[n + 1];
                __nv_bfloat16 h0 = __float2bfloat16(v0);
                __nv_bfloat16 h1 = __float2bfloat16(v1);
                __nv_bfloat16 e0 = __float2bfloat16(v0 - __bfloat162float(h0));
                __nv_bfloat16 e1 = __float2bfloat16(v1 - __bfloat162float(h1));
                *(__nv_bfloat162*)(hip + off) = __nv_bfloat162(h0, h1);
                *(__nv_bfloat162*)(lop + off) = __nv_bfloat162(e0, e1);
            }
        }
    }
}

// ---------------------------------------------------------------------------
// FA2-style HMMA attention (proven R8): CTA = (qt, g, b*h), 128 thr, 4 warps
// ---------------------------------------------------------------------------
#define AQ_STR  528              // bytes per Q/K row (256 bf16 + 8 pad)
#define AV_STR  272              // bytes per V row (128 bf16 + 8 pad)
#define OFF_AK  33792            // 64*528
#define OFF_AVH 67584
#define OFF_AVL 84992
#define AT_SMEM 102400           // -> 2 CTAs/SM

__global__ __launch_bounds__(128, 2) void attn_kernel(float* __restrict__ y)
{
    extern __shared__ char smc[];
    const uint32_t smb = s2u(smc);
    const int tid  = threadIdx.x;
    const int w    = tid >> 5, lane = tid & 31;
    const int lrow = lane & 15, lcol = (lane >> 4) * 8;

    const int qt = blockIdx.x;               // 0..3
    const int g  = blockIdx.y;               // 0..31
    const int bh = blockIdx.z;
    const int b  = bh >> 4;
    const int h  = bh & 15;

    const size_t TOT   = (size_t)B_ * H_ * N_ * HD_;
    const size_t plane = ((size_t)b * H_ + h) * (size_t)N_ * HD_;
    const __nv_bfloat16* qh = g_hi + plane + (size_t)(g * GS_ + qt * 64) * HD_;
    const __nv_bfloat16* ql = g_lo + plane + (size_t)(g * GS_ + qt * 64) * HD_;
    const __nv_bfloat16* kh = g_hi + TOT     + plane + (size_t)(g * GS_) * HD_;
    const __nv_bfloat16* kl = g_lo + TOT     + plane + (size_t)(g * GS_) * HD_;
    const __nv_bfloat16* vh = g_hi + 2 * TOT + plane + (size_t)(g * GS_) * HD_;
    const __nv_bfloat16* vl = g_lo + 2 * TOT + plane + (size_t)(g * GS_) * HD_;

    // load Q tile: [Qh | Ql], 64 rows x 528 B
    #pragma unroll
    for (int i = 0; i < 8; i++) {
        int f = tid + 128 * i, r = f >> 4, c8 = (f & 15) * 8;
        *(uint4*)(smc + r * AQ_STR + 2 * c8) =
            *(const uint4*)(qh + (size_t)r * HD_ + c8);
        *(uint4*)(smc + r * AQ_STR + 256 + 2 * c8) =
            *(const uint4*)(ql + (size_t)r * HD_ + c8);
    }

    float m0 = -1e30f, m1 = -1e30f, l0 = 0.f, l1 = 0.f;
    float accO[16][4];
    #pragma unroll
    for (int i = 0; i < 16; i++)
        #pragma unroll
        for (int j = 0; j < 4; j++) accO[i][j] = 0.f;

    for (int kt = 0; kt <= qt; kt++) {
        __syncthreads();     // prev V reads done / Q store visible (first iter)
        #pragma unroll
        for (int i = 0; i < 8; i++) {
            int f = tid + 128 * i, r = f >> 4, c8 = (f & 15) * 8;
            const size_t go = (size_t)(kt * 64 + r) * HD_ + c8;
            *(uint4*)(smc + OFF_AK + r * AQ_STR + 2 * c8)        = *(const uint4*)(kh + go);
            *(uint4*)(smc + OFF_AK + r * AQ_STR + 256 + 2 * c8)  = *(const uint4*)(kl + go);
            *(uint4*)(smc + OFF_AVH + r * AV_STR + 2 * c8)       = *(const uint4*)(vh + go);
            *(uint4*)(smc + OFF_AVL + r * AV_STR + 2 * c8)       = *(const uint4*)(vl + go);
        }
        __syncthreads();

        // ---- S = Qaug . Kaug^T  (3 passes, k=128 each) ----
        float s[8][4];
        #pragma unroll
        for (int i = 0; i < 8; i++)
            #pragma unroll
            for (int j = 0; j < 4; j++) s[i][j] = 0.f;

        #pragma unroll
        for (int pass = 0; pass < 3; pass++) {
            const int qoff = (pass == 1) ? 256 : 0;    // bytes: Ql at +256
            const int koff = (pass == 2) ? 256 : 0;    // bytes: Kl at +256
            #pragma unroll
            for (int ks = 0; ks < 8; ks++) {
                uint32_t afr[4];
                ldmx4(afr, smb + (w * 16 + lrow) * AQ_STR + qoff + 2 * (ks * 16 + lcol));
                #pragma unroll
                for (int nb = 0; nb < 4; nb++) {
                    uint32_t bm[4];
                    ldmx4(bm, smb + OFF_AK + (nb * 16 + lrow) * AQ_STR + koff
                               + 2 * (ks * 16 + lcol));
                    mma16816(s[nb * 2],     afr, bm[0], bm[2]);
                    mma16816(s[nb * 2 + 1], afr, bm[1], bm[3]);
                }
            }
        }

        // ---- scale + causal mask (diagonal tile only) ----
        #pragma unroll
        for (int nt = 0; nt < 8; nt++)
            #pragma unroll
            for (int j = 0; j < 4; j++) s[nt][j] *= SCALE_;
        if (kt == qt) {
            const int r0 = w * 16 + (lane >> 2);
            const int r1 = r0 + 8;
            #pragma unroll
            for (int nt = 0; nt < 8; nt++) {
                const int col = nt * 8 + (lane & 3) * 2;
                if (col     > r0) s[nt][0] = NEGF;
                if (col + 1 > r0) s[nt][1] = NEGF;
                if (col     > r1) s[nt][2] = NEGF;
                if (col + 1 > r1) s[nt][3] = NEGF;
            }
        }

        // ---- online softmax (rows r0, r1) ----
        float tm0 = -1e30f, tm1 = -1e30f;
        #pragma unroll
        for (int nt = 0; nt < 8; nt++) {
            tm0 = fmaxf(tm0, fmaxf(s[nt][0], s[nt][1]));
            tm1 = fmaxf(tm1, fmaxf(s[nt][2], s[nt][3]));
        }
        tm0 = fmaxf(tm0, __shfl_xor_sync(~0u, tm0, 1));
        tm0 = fmaxf(tm0, __shfl_xor_sync(~0u, tm0, 2));
        tm1 = fmaxf(tm1, __shfl_xor_sync(~0u, tm1, 1));
        tm1 = fmaxf(tm1, __shfl_xor_sync(~0u, tm1, 2));

        const float mn0 = fmaxf(m0, tm0), mn1 = fmaxf(m1, tm1);
        const float a0 = __expf(m0 - mn0), a1 = __expf(m1 - mn1);
        float rs0 = 0.f, rs1 = 0.f;
        #pragma unroll
        for (int nt = 0; nt < 8; nt++) {
            s[nt][0] = __expf(s[nt][0] - mn0); rs0 += s[nt][0];
            s[nt][1] = __expf(s[nt][1] - mn0); rs0 += s[nt][1];
            s[nt][2] = __expf(s[nt][2] - mn1); rs1 += s[nt][2];
            s[nt][3] = __expf(s[nt][3] - mn1); rs1 += s[nt][3];
        }
        rs0 += __shfl_xor_sync(~0u, rs0, 1); rs0 += __shfl_xor_sync(~0u, rs0, 2);
        rs1 += __shfl_xor_sync(~0u, rs1, 1); rs1 += __shfl_xor_sync(~0u, rs1, 2);
        l0 = l0 * a0 + rs0;  l1 = l1 * a1 + rs1;
        m0 = mn0;            m1 = mn1;
        #pragma unroll
        for (int dt = 0; dt < 16; dt++) {
            accO[dt][0] *= a0; accO[dt][1] *= a0;
            accO[dt][2] *= a1; accO[dt][3] *= a1;
        }

        // ---- P (C-frag -> A-frag, hi/lo) . V ----
        #pragma unroll
        for (int kk = 0; kk < 4; kk++) {
            uint32_t ph[4], pl[4];
            auto mk = [&](float p0, float p1, uint32_t& hh, uint32_t& ll) {
                __nv_bfloat16 c0 = __float2bfloat16(p0);
                __nv_bfloat16 c1 = __float2bfloat16(p1);
                __nv_bfloat162 hv(c0, c1);
                hh = *(uint32_t*)&hv;
                __nv_bfloat162 lv(__float2bfloat16(p0 - __bfloat162float(c0)),
                                  __float2bfloat16(p1 - __bfloat162float(c1)));
                ll = *(uint32_t*)&lv;
            };
            mk(s[2 * kk][0],     s[2 * kk][1],     ph[0], pl[0]);
            mk(s[2 * kk][2],     s[2 * kk][3],     ph[1], pl[1]);
            mk(s[2 * kk + 1][0], s[2 * kk + 1][1], ph[2], pl[2]);
            mk(s[2 * kk + 1][2], s[2 * kk + 1][3], ph[3], pl[3]);
            #pragma unroll
            for (int dt = 0; dt < 8; dt++) {
                uint32_t bm[4];
                ldmx4t(bm, smb + OFF_AVH + (kk * 16 + lrow) * AV_STR
                            + 2 * (dt * 16 + lcol));
                mma16816(accO[dt * 2],     ph, bm[0], bm[1]);
                mma16816(accO[dt * 2 + 1], ph, bm[2], bm[3]);
                mma16816(accO[dt * 2],     pl, bm[0], bm[1]);
                mma16816(accO[dt * 2 + 1], pl, bm[2], bm[3]);
                ldmx4t(bm, smb + OFF_AVL + (kk * 16 + lrow) * AV_STR
                            + 2 * (dt * 16 + lcol));
                mma16816(accO[dt * 2],     ph, bm[0], bm[1]);
                mma16816(accO[dt * 2 + 1], ph, bm[2], bm[3]);
            }
        }
    }

    // ---- epilogue: normalize, unshift + head-interleave into y ----
    const float i0 = 1.f / l0, i1 = 1.f / l1;
    const int row = w * 16 + (lane >> 2);
    const int np0 = g * GS_ + qt * 64 + row;
    const int np1 = np0 + 8;
    const int nf0 = (h < HALF_) ? np0 : ((np0 + SHIFT_) & (N_ - 1));
    const int nf1 = (h < HALF_) ? np1 : ((np1 + SHIFT_) & (N_ - 1));
    float* y0 = y + ((size_t)b * N_ + nf0) * C_ + h * HD_;
    float* y1 = y + ((size_t)b * N_ + nf1) * C_ + h * HD_;
    #pragma unroll
    for (int dt = 0; dt < 16; dt++) {
        const int d = dt * 8 + (lane & 3) * 2;
        *(float2*)(y0 + d) = make_float2(accO[dt][0] * i0, accO[dt][1] * i0);
        *(float2*)(y1 + d) = make_float2(accO[dt][2] * i1, accO[dt][3] * i1);
    }
}

// ---------------------------------------------------------------------------
extern "C" void kernel_launch(void* const* d_in, const int* in_sizes, int n_in,
                              void* d_out, int out_size)
{
    const float* x  = (const float*)d_in[0];
    const float* Wq = (const float*)d_in[1];
    const float* bq = (const float*)d_in[2];
    const float* Wk = (const float*)d_in[3];
    const float* bk = (const float*)d_in[4];
    const float* Wv = (const float*)d_in[5];
    const float* bv = (const float*)d_in[6];
    float* y = (float*)d_out;

    __nv_bfloat16 *Ag, *Bg;
    cudaGetSymbolAddress((void**)&Ag, g_A);
    cudaGetSymbolAddress((void**)&Bg, g_B);

    // hi/lo splits: A = [hi|lo|hi], B = [hi|hi|lo]
    split_kernel<<<MROWS * 2, 256>>>(x,  Ag, 2 * C_, C_);
    split_kernel<<<C_ * 2,    256>>>(Wq, Bg + (size_t)0 * C_ * K6, C_, 2 * C_);
    split_kernel<<<C_ * 2,    256>>>(Wk, Bg + (size_t)1 * C_ * K6, C_, 2 * C_);
    split_kernel<<<C_ * 2,    256>>>(Wv, Bg + (size_t)2 * C_ * K6, C_, 2 * C_);

    // HMMA projections v4b (KC=64, 3-stage, 2 CTA/SM, 16B-aligned rows)
    cudaFuncSetAttribute(gemm_kernel,
                         cudaFuncAttributeMaxDynamicSharedMemorySize, GM_SMEM);
    gemm_kernel<<<dim3(C_ / 128, MROWS / 128, 3), 256, GM_SMEM>>>(bq, bk, bv);

    // FA2-style attention
    cudaFuncSetAttribute(attn_kernel,
                         cudaFuncAttributeMaxDynamicSharedMemorySize, AT_SMEM);
    attn_kernel<<<dim3(4, G_, B_ * H_), 128, AT_SMEM>>>(y);
}

// round 11
// speedup vs baseline: 1.3156x; 1.0131x over previous
#include <cuda_runtime.h>
#include <cuda_bf16.h>
#include <math.h>
#include <stdint.h>

// ---------------------------------------------------------------------------
// Problem constants
// ---------------------------------------------------------------------------
#define B_    2
#define N_    8192
#define C_    2048
#define H_    16
#define HD_   128
#define GS_   256
#define G_    (N_/GS_)     // 32
#define HALF_ 8
#define SHIFT_ 128
#define SCALE_ 0.08838834764831843f   // 1/sqrt(128)
#define NEGF  -1e9f

#define MROWS (B_*N_)      // 16384
#define K6    (3*C_)       // 6144 augmented K: [hi|lo|hi] x [hi|hi|lo]

// scratch
__device__ __nv_bfloat16 g_A[(size_t)MROWS * K6];            // x_aug  [16384][6144]
__device__ __nv_bfloat16 g_B[(size_t)3 * C_ * K6];           // W_aug  [3][2048][6144]
__device__ __nv_bfloat16 g_hi[(size_t)3 * B_ * H_ * N_ * HD_];  // qkv hi (shifted)
__device__ __nv_bfloat16 g_lo[(size_t)3 * B_ * H_ * N_ * HD_];  // qkv lo (shifted)

// ---------------------------------------------------------------------------
// split: fp32 [rows][2048] -> bf16 [rows][6144]; hi at col 0 and hi2_off, lo at lo_off
// ---------------------------------------------------------------------------
__global__ __launch_bounds__(256) void split_kernel(
    const float* __restrict__ in, __nv_bfloat16* __restrict__ out,
    int hi2_off, int lo_off)
{
    size_t idx = (size_t)blockIdx.x * 256 + threadIdx.x;   // one float4 each
    float4 v = ((const float4*)in)[idx];
    size_t m  = idx >> 9;          // 512 float4 per row
    int    c  = (int)(idx & 511) * 4;

    __nv_bfloat16 h0 = __float2bfloat16(v.x);
    __nv_bfloat16 h1 = __float2bfloat16(v.y);
    __nv_bfloat16 h2 = __float2bfloat16(v.z);
    __nv_bfloat16 h3 = __float2bfloat16(v.w);
    __nv_bfloat16 l0 = __float2bfloat16(v.x - __bfloat162float(h0));
    __nv_bfloat16 l1 = __float2bfloat16(v.y - __bfloat162float(h1));
    __nv_bfloat16 l2 = __float2bfloat16(v.z - __bfloat162float(h2));
    __nv_bfloat16 l3 = __float2bfloat16(v.w - __bfloat162float(h3));

    __nv_bfloat162 hA(h0, h1), hB(h2, h3), lA(l0, l1), lB(l2, l3);
    __nv_bfloat16* rowp = out + m * K6;
    *(__nv_bfloat162*)(rowp + c)               = hA;
    *(__nv_bfloat162*)(rowp + c + 2)           = hB;
    *(__nv_bfloat162*)(rowp + hi2_off + c)     = hA;
    *(__nv_bfloat162*)(rowp + hi2_off + c + 2) = hB;
    *(__nv_bfloat162*)(rowp + lo_off + c)      = lA;
    *(__nv_bfloat162*)(rowp + lo_off + c + 2)  = lB;
}

// ---------------------------------------------------------------------------
// common MMA helpers (proven R5-R10)
// ---------------------------------------------------------------------------
__device__ __forceinline__ uint32_t s2u(const void* p) {
    uint32_t a;
    asm("{ .reg .u64 t; cvta.to.shared.u64 t, %1; cvt.u32.u64 %0, t; }"
        : "=r"(a) : "l"(p));
    return a;
}
__device__ __forceinline__ void ldmx4(uint32_t* r, uint32_t addr) {
    asm volatile("ldmatrix.sync.aligned.m8n8.x4.shared.b16 {%0,%1,%2,%3}, [%4];"
                 : "=r"(r[0]), "=r"(r[1]), "=r"(r[2]), "=r"(r[3]) : "r"(addr));
}
__device__ __forceinline__ void ldmx4t(uint32_t* r, uint32_t addr) {
    asm volatile("ldmatrix.sync.aligned.m8n8.x4.trans.shared.b16 {%0,%1,%2,%3}, [%4];"
                 : "=r"(r[0]), "=r"(r[1]), "=r"(r[2]), "=r"(r[3]) : "r"(addr));
}
__device__ __forceinline__ void mma16816(float* c, const uint32_t* a,
                                         uint32_t b0, uint32_t b1) {
    asm volatile(
        "mma.sync.aligned.m16n8k16.row.col.f32.bf16.bf16.f32 "
        "{%0,%1,%2,%3}, {%4,%5,%6,%7}, {%8,%9}, {%0,%1,%2,%3};"
        : "+f"(c[0]), "+f"(c[1]), "+f"(c[2]), "+f"(c[3])
        : "r"(a[0]), "r"(a[1]), "r"(a[2]), "r"(a[3]), "r"(b0), "r"(b1));
}
__device__ __forceinline__ void cp16(uint32_t dst, const void* src) {
    asm volatile("cp.async.cg.shared.global [%0], [%1], 16;"
                 :: "r"(dst), "l"(src) : "memory");
}

// ---------------------------------------------------------------------------
// HMMA GEMM v4b (proven R10): tile 128x128, warp 32x64, KC=64, 3-stage, 2 CTA/SM
// ---------------------------------------------------------------------------
#define KC      64
#define NCH     (K6/KC)        // 96
#define GROWB   144            // 64 bf16 (128 B) + 16 pad (16B-aligned rows)
#define GSTAGE  (256*GROWB)    // 36864 B
#define GM_SMEM (3*GSTAGE)     // 110592 B -> 2 CTAs/SM

__global__ __launch_bounds__(256, 2) void gemm_kernel(
    const float* __restrict__ bq, const float* __restrict__ bk,
    const float* __restrict__ bv)
{
    extern __shared__ char smg[];
    const uint32_t smb = s2u(smg);

    const int tid  = threadIdx.x;
    const int wid  = tid >> 5, lane = tid & 31;
    const int wm   = wid & 3;
    const int wn   = wid >> 2;
    const int lrow = lane & 15;
    const int lcol = (lane >> 4) * 8;

    const int n0 = blockIdx.x * 128;
    const int m0 = blockIdx.y * 128;
    const int z  = blockIdx.z;
    const __nv_bfloat16* __restrict__ Ap = g_A + (size_t)m0 * K6;
    const __nv_bfloat16* __restrict__ Bp = g_B + (size_t)z * C_ * K6 + (size_t)n0 * K6;
    const float* __restrict__ bias = (z == 0) ? bq : (z == 1) ? bk : bv;

    float acc[2][8][4];
    #pragma unroll
    for (int i = 0; i < 2; i++)
        #pragma unroll
        for (int j = 0; j < 8; j++)
            #pragma unroll
            for (int k = 0; k < 4; k++) acc[i][j][k] = 0.f;

    auto fetch = [&](int c) {
        const int s = c - (c / 3) * 3;
        const size_t k0 = (size_t)c * KC;
        const uint32_t base = smb + s * GSTAGE;
        #pragma unroll
        for (int i = 0; i < 4; i++) {
            int f = tid + 256 * i, row = f >> 3, cc = (f & 7) * 16;
            cp16(base + row * GROWB + cc, Ap + (size_t)row * K6 + k0 + cc / 2);
        }
        #pragma unroll
        for (int i = 0; i < 4; i++) {
            int f = tid + 256 * i, row = f >> 3, cc = (f & 7) * 16;
            cp16(base + 128 * GROWB + row * GROWB + cc,
                 Bp + (size_t)row * K6 + k0 + cc / 2);
        }
        asm volatile("cp.async.commit_group;" ::: "memory");
    };

    fetch(0); fetch(1);

    for (int c = 0; c < NCH; c++) {
        if (c + 1 < NCH) asm volatile("cp.async.wait_group 1;" ::: "memory");
        else             asm volatile("cp.async.wait_group 0;" ::: "memory");
        __syncthreads();
        if (c + 2 < NCH) fetch(c + 2);

        const int s = c - (c / 3) * 3;
        const uint32_t aB = smb + s * GSTAGE;
        const uint32_t bB = aB + 128 * GROWB;
        #pragma unroll
        for (int ks = 0; ks < 4; ks++) {
            const int kb = 2 * (ks * 16 + lcol);
            uint32_t afr[2][4];
            #pragma unroll
            for (int mi = 0; mi < 2; mi++)
                ldmx4(afr[mi], aB + (wm * 32 + mi * 16 + lrow) * GROWB + kb);
            #pragma unroll
            for (int nb = 0; nb < 4; nb++) {
                uint32_t bm[4];
                ldmx4(bm, bB + (wn * 64 + nb * 16 + lrow) * GROWB + kb);
                #pragma unroll
                for (int mi = 0; mi < 2; mi++) {
                    mma16816(acc[mi][2 * nb],     afr[mi], bm[0], bm[2]);
                    mma16816(acc[mi][2 * nb + 1], afr[mi], bm[1], bm[3]);
                }
            }
        }
    }

    // epilogue: fragments -> g_hi/g_lo (bias + shift), bf16 hi/lo
    const size_t PSZ = (size_t)B_ * H_ * N_ * HD_;
    __nv_bfloat16* hip = g_hi + (size_t)z * PSZ;
    __nv_bfloat16* lop = g_lo + (size_t)z * PSZ;
    const int qrow = lane >> 2;
    const int qcol = (lane & 3) * 2;

    #pragma unroll
    for (int mi = 0; mi < 2; mi++) {
        #pragma unroll
        for (int hf = 0; hf < 2; hf++) {
            const int m  = m0 + wm * 32 + mi * 16 + qrow + hf * 8;
            const int b  = m >> 13;
            const int ns = m & (N_ - 1);
            #pragma unroll
            for (int ni = 0; ni < 8; ni++) {
                const int n = n0 + wn * 64 + ni * 8 + qcol;
                const int hh = n >> 7;
                const int d  = n & (HD_ - 1);
                const int nd = (hh < HALF_) ? ns : ((ns - SHIFT_) & (N_ - 1));
                const size_t off = (((size_t)b * H_ + hh) * N_ + nd) * HD_ + d;
                float v0 = acc[mi][ni][hf * 2 + 0] + bias[n];
                float v1 = acc[mi][ni][hf * 2 + 1] + bias[n + 1];
                __nv_bfloat16 h0 = __float2bfloat16(v0);
                __nv_bfloat16 h1 = __float2bfloat16(v1);
                __nv_bfloat16 e0 = __float2bfloat16(v0 - __bfloat162float(h0));
                __nv_bfloat16 e1 = __float2bfloat16(v1 - __bfloat162float(h1));
                *(__nv_bfloat162*)(hip + off) = __nv_bfloat162(h0, h1);
                *(__nv_bfloat162*)(lop + off) = __nv_bfloat162(e0, e1);
            }
        }
    }
}

// ---------------------------------------------------------------------------
// FA2-style HMMA attention v3: CTA = (qt, g, b*h), 128 thr, 4 warps.
// K/V processed in 32-row chunks, double-buffered via cp.async.
// Row layouts (stride 528 B): Q/K: [hi 256B | lo 256B | pad], V: [Vh | Vl | pad]
// ---------------------------------------------------------------------------
#define AQ_STR  528
#define KCH_B   (32*AQ_STR)      // 16896 per chunk buffer
#define OFF_AK  (64*AQ_STR)      // 33792 (after Q)
#define OFF_AV  (OFF_AK + 2*KCH_B)  // 67584
#define AT_SMEM (OFF_AV + 2*KCH_B)  // 101376 -> 2 CTAs/SM

__global__ __launch_bounds__(128, 2) void attn_kernel(float* __restrict__ y)
{
    extern __shared__ char smc[];
    const uint32_t smb = s2u(smc);
    const int tid  = threadIdx.x;
    const int w    = tid >> 5, lane = tid & 31;
    const int lrow = lane & 15, lcol = (lane >> 4) * 8;

    const int qt = blockIdx.x;               // 0..3
    const int g  = blockIdx.y;               // 0..31
    const int bh = blockIdx.z;
    const int b  = bh >> 4;
    const int h  = bh & 15;

    const size_t TOT   = (size_t)B_ * H_ * N_ * HD_;
    const size_t plane = ((size_t)b * H_ + h) * (size_t)N_ * HD_;
    const __nv_bfloat16* qh = g_hi + plane + (size_t)(g * GS_ + qt * 64) * HD_;
    const __nv_bfloat16* ql = g_lo + plane + (size_t)(g * GS_ + qt * 64) * HD_;
    const __nv_bfloat16* kh = g_hi + TOT     + plane + (size_t)(g * GS_) * HD_;
    const __nv_bfloat16* kl = g_lo + TOT     + plane + (size_t)(g * GS_) * HD_;
    const __nv_bfloat16* vh = g_hi + 2 * TOT + plane + (size_t)(g * GS_) * HD_;
    const __nv_bfloat16* vl = g_lo + 2 * TOT + plane + (size_t)(g * GS_) * HD_;

    // load Q tile: [Qh | Ql], 64 rows x 528 B (sync; once per CTA)
    #pragma unroll
    for (int i = 0; i < 8; i++) {
        int f = tid + 128 * i, r = f >> 4, c8 = (f & 15) * 8;
        *(uint4*)(smc + r * AQ_STR + 2 * c8) =
            *(const uint4*)(qh + (size_t)r * HD_ + c8);
        *(uint4*)(smc + r * AQ_STR + 256 + 2 * c8) =
            *(const uint4*)(ql + (size_t)r * HD_ + c8);
    }

    // async fetch of 32-row K/V chunk c into buffer c&1
    auto fetchkv = [&](int c) {
        const int bsel = c & 1;
        const uint32_t kb = smb + OFF_AK + bsel * KCH_B;
        const uint32_t vb = smb + OFF_AV + bsel * KCH_B;
        #pragma unroll
        for (int i = 0; i < 8; i++) {
            int f = tid + 128 * i;        // 0..1023
            int r = f >> 5;               // 0..31 chunk row
            int u = f & 31;               // 16B unit within 512B row
            const size_t row = (size_t)(c * 32 + r) * HD_;
            if (u < 16) {
                cp16(kb + r * AQ_STR + u * 16, kh + row + u * 8);
                cp16(vb + r * AQ_STR + u * 16, vh + row + u * 8);
            } else {
                cp16(kb + r * AQ_STR + u * 16, kl + row + (u - 16) * 8);
                cp16(vb + r * AQ_STR + u * 16, vl + row + (u - 16) * 8);
            }
        }
        asm volatile("cp.async.commit_group;" ::: "memory");
    };

    float m0 = -1e30f, m1 = -1e30f, l0 = 0.f, l1 = 0.f;
    float accO[16][4];
    #pragma unroll
    for (int i = 0; i < 16; i++)
        #pragma unroll
        for (int j = 0; j < 4; j++) accO[i][j] = 0.f;

    const int NCHK = 2 * (qt + 1);
    fetchkv(0);

    for (int c = 0; c < NCHK; c++) {
        if (c + 1 < NCHK) {
            fetchkv(c + 1);
            asm volatile("cp.async.wait_group 1;" ::: "memory");
        } else {
            asm volatile("cp.async.wait_group 0;" ::: "memory");
        }
        __syncthreads();   // chunk c visible (also Q stores on first iter)

        const uint32_t kbuf = smb + OFF_AK + (c & 1) * KCH_B;
        const uint32_t vbuf = smb + OFF_AV + (c & 1) * KCH_B;

        // ---- S = Qaug . Kaug^T for 32 K-rows (3 passes, k=128 each) ----
        float s[4][4];
        #pragma unroll
        for (int i = 0; i < 4; i++)
            #pragma unroll
            for (int j = 0; j < 4; j++) s[i][j] = 0.f;

        #pragma unroll
        for (int pass = 0; pass < 3; pass++) {
            const int qoff = (pass == 1) ? 256 : 0;    // Ql at byte 256
            const int koff = (pass == 2) ? 256 : 0;    // Kl at byte 256
            #pragma unroll
            for (int ks = 0; ks < 8; ks++) {
                uint32_t afr[4];
                ldmx4(afr, smb + (w * 16 + lrow) * AQ_STR + qoff + 2 * (ks * 16 + lcol));
                #pragma unroll
                for (int nb = 0; nb < 2; nb++) {
                    uint32_t bm[4];
                    ldmx4(bm, kbuf + (nb * 16 + lrow) * AQ_STR + koff
                               + 2 * (ks * 16 + lcol));
                    mma16816(s[nb * 2],     afr, bm[0], bm[2]);
                    mma16816(s[nb * 2 + 1], afr, bm[1], bm[3]);
                }
            }
        }

        // ---- scale + causal mask (only tail chunks can mask) ----
        #pragma unroll
        for (int nt = 0; nt < 4; nt++)
            #pragma unroll
            for (int j = 0; j < 4; j++) s[nt][j] *= SCALE_;
        if (c >= 2 * qt) {
            const int r0 = qt * 64 + w * 16 + (lane >> 2);
            const int r1 = r0 + 8;
            #pragma unroll
            for (int nt = 0; nt < 4; nt++) {
                const int col = c * 32 + nt * 8 + (lane & 3) * 2;
                if (col     > r0) s[nt][0] = NEGF;
                if (col + 1 > r0) s[nt][1] = NEGF;
                if (col     > r1) s[nt][2] = NEGF;
                if (col + 1 > r1) s[nt][3] = NEGF;
            }
        }

        // ---- online softmax (rows r0, r1) ----
        float tm0 = -1e30f, tm1 = -1e30f;
        #pragma unroll
        for (int nt = 0; nt < 4; nt++) {
            tm0 = fmaxf(tm0, fmaxf(s[nt][0], s[nt][1]));
            tm1 = fmaxf(tm1, fmaxf(s[nt][2], s[nt][3]));
        }
        tm0 = fmaxf(tm0, __shfl_xor_sync(~0u, tm0, 1));
        tm0 = fmaxf(tm0, __shfl_xor_sync(~0u, tm0, 2));
        tm1 = fmaxf(tm1, __shfl_xor_sync(~0u, tm1, 1));
        tm1 = fmaxf(tm1, __shfl_xor_sync(~0u, tm1, 2));

        const float mn0 = fmaxf(m0, tm0), mn1 = fmaxf(m1, tm1);
        const float a0 = __expf(m0 - mn0), a1 = __expf(m1 - mn1);
        float rs0 = 0.f, rs1 = 0.f;
        #pragma unroll
        for (int nt = 0; nt < 4; nt++) {
            s[nt][0] = __expf(s[nt][0] - mn0); rs0 += s[nt][0];
            s[nt][1] = __expf(s[nt][1] - mn0); rs0 += s[nt][1];
            s[nt][2] = __expf(s[nt][2] - mn1); rs1 += s[nt][2];
            s[nt][3] = __expf(s[nt][3] - mn1); rs1 += s[nt][3];
        }
        rs0 += __shfl_xor_sync(~0u, rs0, 1); rs0 += __shfl_xor_sync(~0u, rs0, 2);
        rs1 += __shfl_xor_sync(~0u, rs1, 1); rs1 += __shfl_xor_sync(~0u, rs1, 2);
        l0 = l0 * a0 + rs0;  l1 = l1 * a1 + rs1;
        m0 = mn0;            m1 = mn1;
        #pragma unroll
        for (int dt = 0; dt < 16; dt++) {
            accO[dt][0] *= a0; accO[dt][1] *= a0;
            accO[dt][2] *= a1; accO[dt][3] *= a1;
        }

        // ---- P (C-frag -> A-frag, hi/lo) . V (32 rows) ----
        #pragma unroll
        for (int kk = 0; kk < 2; kk++) {
            uint32_t ph[4], pl[4];
            auto mk = [&](float p0, float p1, uint32_t& hh, uint32_t& ll) {
                __nv_bfloat16 c0 = __float2bfloat16(p0);
                __nv_bfloat16 c1 = __float2bfloat16(p1);
                __nv_bfloat162 hv(c0, c1);
                hh = *(uint32_t*)&hv;
                __nv_bfloat162 lv(__float2bfloat16(p0 - __bfloat162float(c0)),
                                  __float2bfloat16(p1 - __bfloat162float(c1)));
                ll = *(uint32_t*)&lv;
            };
            mk(s[2 * kk][0],     s[2 * kk][1],     ph[0], pl[0]);
            mk(s[2 * kk][2],     s[2 * kk][3],     ph[1], pl[1]);
            mk(s[2 * kk + 1][0], s[2 * kk + 1][1], ph[2], pl[2]);
            mk(s[2 * kk + 1][2], s[2 * kk + 1][3], ph[3], pl[3]);
            #pragma unroll
            for (int dt = 0; dt < 8; dt++) {
                uint32_t bm[4];
                ldmx4t(bm, vbuf + (kk * 16 + lrow) * AQ_STR
                            + 2 * (dt * 16 + lcol));
                mma16816(accO[dt * 2],     ph, bm[0], bm[1]);
                mma16816(accO[dt * 2 + 1], ph, bm[2], bm[3]);
                mma16816(accO[dt * 2],     pl, bm[0], bm[1]);
                mma16816(accO[dt * 2 + 1], pl, bm[2], bm[3]);
                ldmx4t(bm, vbuf + (kk * 16 + lrow) * AQ_STR + 256
                            + 2 * (dt * 16 + lcol));
                mma16816(accO[dt * 2],     ph, bm[0], bm[1]);
                mma16816(accO[dt * 2 + 1], ph, bm[2], bm[3]);
            }
        }
        __syncthreads();   // all reads of buffer c&1 done before it is refilled
    }

    // ---- epilogue: normalize, unshift + head-interleave into y ----
    const float i0 = 1.f / l0, i1 = 1.f / l1;
    const int row = w * 16 + (lane >> 2);
    const int np0 = g * GS_ + qt * 64 + row;
    const int np1 = np0 + 8;
    const int nf0 = (h < HALF_) ? np0 : ((np0 + SHIFT_) & (N_ - 1));
    const int nf1 = (h < HALF_) ? np1 : ((np1 + SHIFT_) & (N_ - 1));
    float* y0 = y + ((size_t)b * N_ + nf0) * C_ + h * HD_;
    float* y1 = y + ((size_t)b * N_ + nf1) * C_ + h * HD_;
    #pragma unroll
    for (int dt = 0; dt < 16; dt++) {
        const int d = dt * 8 + (lane & 3) * 2;
        *(float2*)(y0 + d) = make_float2(accO[dt][0] * i0, accO[dt][1] * i0);
        *(float2*)(y1 + d) = make_float2(accO[dt][2] * i1, accO[dt][3] * i1);
    }
}

// ---------------------------------------------------------------------------
extern "C" void kernel_launch(void* const* d_in, const int* in_sizes, int n_in,
                              void* d_out, int out_size)
{
    const float* x  = (const float*)d_in[0];
    const float* Wq = (const float*)d_in[1];
    const float* bq = (const float*)d_in[2];
    const float* Wk = (const float*)d_in[3];
    const float* bk = (const float*)d_in[4];
    const float* Wv = (const float*)d_in[5];
    const float* bv = (const float*)d_in[6];
    float* y = (float*)d_out;

    __nv_bfloat16 *Ag, *Bg;
    cudaGetSymbolAddress((void**)&Ag, g_A);
    cudaGetSymbolAddress((void**)&Bg, g_B);

    // hi/lo splits: A = [hi|lo|hi], B = [hi|hi|lo]
    split_kernel<<<MROWS * 2, 256>>>(x,  Ag, 2 * C_, C_);
    split_kernel<<<C_ * 2,    256>>>(Wq, Bg + (size_t)0 * C_ * K6, C_, 2 * C_);
    split_kernel<<<C_ * 2,    256>>>(Wk, Bg + (size_t)1 * C_ * K6, C_, 2 * C_);
    split_kernel<<<C_ * 2,    256>>>(Wv, Bg + (size_t)2 * C_ * K6, C_, 2 * C_);

    // HMMA projections v4b (proven R10)
    cudaFuncSetAttribute(gemm_kernel,
                         cudaFuncAttributeMaxDynamicSharedMemorySize, GM_SMEM);
    gemm_kernel<<<dim3(C_ / 128, MROWS / 128, 3), 256, GM_SMEM>>>(bq, bk, bv);

    // FA2-style attention v3 (cp.async chunked K/V pipeline)
    cudaFuncSetAttribute(attn_kernel,
                         cudaFuncAttributeMaxDynamicSharedMemorySize, AT_SMEM);
    attn_kernel<<<dim3(4, G_, B_ * H_), 128, AT_SMEM>>>(y);
}

// round 12
// speedup vs baseline: 2.0409x; 1.5513x over previous
#include <cuda_runtime.h>
#include <cuda_fp16.h>
#include <math.h>
#include <stdint.h>

// ---------------------------------------------------------------------------
// Problem constants
// ---------------------------------------------------------------------------
#define B_    2
#define N_    8192
#define C_    2048
#define H_    16
#define HD_   128
#define GS_   256
#define G_    (N_/GS_)     // 32
#define HALF_ 8
#define SHIFT_ 128
#define SCALE_ 0.08838834764831843f   // 1/sqrt(128)
#define NEGF  -1e9f

#define MROWS (B_*N_)      // 16384
#define K4    (2*C_)       // 4096 augmented K: [Ah|Al] x [Bh|Bh]

// scratch
__device__ __half g_A[(size_t)MROWS * K4];            // x_aug  [16384][4096]
__device__ __half g_B[(size_t)3 * C_ * K4];           // W_aug  [3][2048][4096]
__device__ __half g_q[(size_t)3 * B_ * H_ * N_ * HD_];   // qkv fp16 (shifted)

// ---------------------------------------------------------------------------
// split: fp32 [rows][2048] -> fp16 [rows][4096]
//   cols 0..2047: hi;  cols 2048..4095: dup_hi ? hi : lo
// ---------------------------------------------------------------------------
__global__ __launch_bounds__(256) void split_kernel(
    const float* __restrict__ in, __half* __restrict__ out, int dup_hi)
{
    size_t idx = (size_t)blockIdx.x * 256 + threadIdx.x;   // one float4 each
    float4 v = ((const float4*)in)[idx];
    size_t m  = idx >> 9;          // 512 float4 per row
    int    c  = (int)(idx & 511) * 4;

    __half h0 = __float2half_rn(v.x);
    __half h1 = __float2half_rn(v.y);
    __half h2 = __float2half_rn(v.z);
    __half h3 = __float2half_rn(v.w);
    __half2 hA = __halves2half2(h0, h1);
    __half2 hB = __halves2half2(h2, h3);

    __half* rowp = out + m * K4;
    *(__half2*)(rowp + c)     = hA;
    *(__half2*)(rowp + c + 2) = hB;
    if (dup_hi) {
        *(__half2*)(rowp + C_ + c)     = hA;
        *(__half2*)(rowp + C_ + c + 2) = hB;
    } else {
        __half l0 = __float2half_rn(v.x - __half2float(h0));
        __half l1 = __float2half_rn(v.y - __half2float(h1));
        __half l2 = __float2half_rn(v.z - __half2float(h2));
        __half l3 = __float2half_rn(v.w - __half2float(h3));
        *(__half2*)(rowp + C_ + c)     = __halves2half2(l0, l1);
        *(__half2*)(rowp + C_ + c + 2) = __halves2half2(l2, l3);
    }
}

// ---------------------------------------------------------------------------
// common MMA helpers (fragment idioms proven R5-R11; dtype now f16)
// ---------------------------------------------------------------------------
__device__ __forceinline__ uint32_t s2u(const void* p) {
    uint32_t a;
    asm("{ .reg .u64 t; cvta.to.shared.u64 t, %1; cvt.u32.u64 %0, t; }"
        : "=r"(a) : "l"(p));
    return a;
}
__device__ __forceinline__ void ldmx4(uint32_t* r, uint32_t addr) {
    asm volatile("ldmatrix.sync.aligned.m8n8.x4.shared.b16 {%0,%1,%2,%3}, [%4];"
                 : "=r"(r[0]), "=r"(r[1]), "=r"(r[2]), "=r"(r[3]) : "r"(addr));
}
__device__ __forceinline__ void ldmx4t(uint32_t* r, uint32_t addr) {
    asm volatile("ldmatrix.sync.aligned.m8n8.x4.trans.shared.b16 {%0,%1,%2,%3}, [%4];"
                 : "=r"(r[0]), "=r"(r[1]), "=r"(r[2]), "=r"(r[3]) : "r"(addr));
}
__device__ __forceinline__ void mma16816(float* c, const uint32_t* a,
                                         uint32_t b0, uint32_t b1) {
    asm volatile(
        "mma.sync.aligned.m16n8k16.row.col.f32.f16.f16.f32 "
        "{%0,%1,%2,%3}, {%4,%5,%6,%7}, {%8,%9}, {%0,%1,%2,%3};"
        : "+f"(c[0]), "+f"(c[1]), "+f"(c[2]), "+f"(c[3])
        : "r"(a[0]), "r"(a[1]), "r"(a[2]), "r"(a[3]), "r"(b0), "r"(b1));
}
__device__ __forceinline__ void cp16(uint32_t dst, const void* src) {
    asm volatile("cp.async.cg.shared.global [%0], [%1], 16;"
                 :: "r"(dst), "l"(src) : "memory");
}

// ---------------------------------------------------------------------------
// HMMA GEMM (R10-proven pipeline, K=4096): tile 128x128, warp 32x64, KC=64,
// 3-stage cp.async, 2 CTAs/SM. Epilogue -> fp16 qkv with bias + shift.
// ---------------------------------------------------------------------------
#define KC      64
#define NCH     (K4/KC)        // 64
#define GROWB   144            // 64 fp16 (128 B) + 16 pad (16B-aligned rows)
#define GSTAGE  (256*GROWB)    // 36864 B
#define GM_SMEM (3*GSTAGE)     // 110592 B -> 2 CTAs/SM

__global__ __launch_bounds__(256, 2) void gemm_kernel(
    const float* __restrict__ bq, const float* __restrict__ bk,
    const float* __restrict__ bv)
{
    extern __shared__ char smg[];
    const uint32_t smb = s2u(smg);

    const int tid  = threadIdx.x;
    const int wid  = tid >> 5, lane = tid & 31;
    const int wm   = wid & 3;
    const int wn   = wid >> 2;
    const int lrow = lane & 15;
    const int lcol = (lane >> 4) * 8;

    const int n0 = blockIdx.x * 128;
    const int m0 = blockIdx.y * 128;
    const int z  = blockIdx.z;
    const __half* __restrict__ Ap = g_A + (size_t)m0 * K4;
    const __half* __restrict__ Bp = g_B + (size_t)z * C_ * K4 + (size_t)n0 * K4;
    const float* __restrict__ bias = (z == 0) ? bq : (z == 1) ? bk : bv;

    float acc[2][8][4];
    #pragma unroll
    for (int i = 0; i < 2; i++)
        #pragma unroll
        for (int j = 0; j < 8; j++)
            #pragma unroll
            for (int k = 0; k < 4; k++) acc[i][j][k] = 0.f;

    auto fetch = [&](int c) {
        const int s = c - (c / 3) * 3;
        const size_t k0 = (size_t)c * KC;
        const uint32_t base = smb + s * GSTAGE;
        #pragma unroll
        for (int i = 0; i < 4; i++) {
            int f = tid + 256 * i, row = f >> 3, cc = (f & 7) * 16;
            cp16(base + row * GROWB + cc, Ap + (size_t)row * K4 + k0 + cc / 2);
        }
        #pragma unroll
        for (int i = 0; i < 4; i++) {
            int f = tid + 256 * i, row = f >> 3, cc = (f & 7) * 16;
            cp16(base + 128 * GROWB + row * GROWB + cc,
                 Bp + (size_t)row * K4 + k0 + cc / 2);
        }
        asm volatile("cp.async.commit_group;" ::: "memory");
    };

    fetch(0); fetch(1);

    for (int c = 0; c < NCH; c++) {
        if (c + 1 < NCH) asm volatile("cp.async.wait_group 1;" ::: "memory");
        else             asm volatile("cp.async.wait_group 0;" ::: "memory");
        __syncthreads();
        if (c + 2 < NCH) fetch(c + 2);

        const int s = c - (c / 3) * 3;
        const uint32_t aB = smb + s * GSTAGE;
        const uint32_t bB = aB + 128 * GROWB;
        #pragma unroll
        for (int ks = 0; ks < 4; ks++) {
            const int kb = 2 * (ks * 16 + lcol);
            uint32_t afr[2][4];
            #pragma unroll
            for (int mi = 0; mi < 2; mi++)
                ldmx4(afr[mi], aB + (wm * 32 + mi * 16 + lrow) * GROWB + kb);
            #pragma unroll
            for (int nb = 0; nb < 4; nb++) {
                uint32_t bm[4];
                ldmx4(bm, bB + (wn * 64 + nb * 16 + lrow) * GROWB + kb);
                #pragma unroll
                for (int mi = 0; mi < 2; mi++) {
                    mma16816(acc[mi][2 * nb],     afr[mi], bm[0], bm[2]);
                    mma16816(acc[mi][2 * nb + 1], afr[mi], bm[1], bm[3]);
                }
            }
        }
    }

    // epilogue: fragments -> g_q (bias + shift), fp16
    const size_t PSZ = (size_t)B_ * H_ * N_ * HD_;
    __half* qp = g_q + (size_t)z * PSZ;
    const int qrow = lane >> 2;
    const int qcol = (lane & 3) * 2;

    #pragma unroll
    for (int mi = 0; mi < 2; mi++) {
        #pragma unroll
        for (int hf = 0; hf < 2; hf++) {
            const int m  = m0 + wm * 32 + mi * 16 + qrow + hf * 8;
            const int b  = m >> 13;
            const int ns = m & (N_ - 1);
            #pragma unroll
            for (int ni = 0; ni < 8; ni++) {
                const int n = n0 + wn * 64 + ni * 8 + qcol;
                const int hh = n >> 7;
                const int d  = n & (HD_ - 1);
                const int nd = (hh < HALF_) ? ns : ((ns - SHIFT_) & (N_ - 1));
                const size_t off = (((size_t)b * H_ + hh) * N_ + nd) * HD_ + d;
                float v0 = acc[mi][ni][hf * 2 + 0] + bias[n];
                float v1 = acc[mi][ni][hf * 2 + 1] + bias[n + 1];
                *(__half2*)(qp + off) = __floats2half2_rn(v0, v1);
            }
        }
    }
}

// ---------------------------------------------------------------------------
// FA2-style fp16 attention: CTA = (qt, g, b*h), 128 thr, 4 warps, 4 CTAs/SM.
// Single-pass QK and PV (fp16 precision). 32-row K/V chunks, double-buffered.
// Row layout: 128 fp16 = 256 B + 16 pad = 272 B stride.
// ---------------------------------------------------------------------------
#define AQ_STR  272
#define KCH_B   (32*AQ_STR)         // 8704 per chunk buffer
#define OFF_AK  (64*AQ_STR)         // 17408 (after Q)
#define OFF_AV  (OFF_AK + 2*KCH_B)  // 34816
#define AT_SMEM (OFF_AV + 2*KCH_B)  // 52224 -> 4 CTAs/SM

__global__ __launch_bounds__(128, 4) void attn_kernel(float* __restrict__ y)
{
    extern __shared__ char smc[];
    const uint32_t smb = s2u(smc);
    const int tid  = threadIdx.x;
    const int w    = tid >> 5, lane = tid & 31;
    const int lrow = lane & 15, lcol = (lane >> 4) * 8;

    const int qt = blockIdx.x;               // 0..3
    const int g  = blockIdx.y;               // 0..31
    const int bh = blockIdx.z;
    const int b  = bh >> 4;
    const int h  = bh & 15;

    const size_t TOT   = (size_t)B_ * H_ * N_ * HD_;
    const size_t plane = ((size_t)b * H_ + h) * (size_t)N_ * HD_;
    const __half* qp = g_q + plane + (size_t)(g * GS_ + qt * 64) * HD_;
    const __half* kp = g_q + TOT     + plane + (size_t)(g * GS_) * HD_;
    const __half* vp = g_q + 2 * TOT + plane + (size_t)(g * GS_) * HD_;

    // load Q tile: 64 rows x 256 B
    #pragma unroll
    for (int i = 0; i < 8; i++) {
        int f = tid + 128 * i, r = f >> 4, c8 = (f & 15) * 8;
        *(uint4*)(smc + r * AQ_STR + 2 * c8) =
            *(const uint4*)(qp + (size_t)r * HD_ + c8);
    }

    // async fetch of 32-row K/V chunk c into buffer c&1
    auto fetchkv = [&](int c) {
        const int bsel = c & 1;
        const uint32_t kb = smb + OFF_AK + bsel * KCH_B;
        const uint32_t vb = smb + OFF_AV + bsel * KCH_B;
        #pragma unroll
        for (int i = 0; i < 4; i++) {
            int f = tid + 128 * i;        // 0..511
            int r = f >> 4;               // 0..31
            int u = f & 15;               // 16B unit
            const size_t row = (size_t)(c * 32 + r) * HD_;
            cp16(kb + r * AQ_STR + u * 16, kp + row + u * 8);
        }
        #pragma unroll
        for (int i = 0; i < 4; i++) {
            int f = tid + 128 * i;
            int r = f >> 4;
            int u = f & 15;
            const size_t row = (size_t)(c * 32 + r) * HD_;
            cp16(vb + r * AQ_STR + u * 16, vp + row + u * 8);
        }
        asm volatile("cp.async.commit_group;" ::: "memory");
    };

    float m0 = -1e30f, m1 = -1e30f, l0 = 0.f, l1 = 0.f;
    float accO[16][4];
    #pragma unroll
    for (int i = 0; i < 16; i++)
        #pragma unroll
        for (int j = 0; j < 4; j++) accO[i][j] = 0.f;

    const int NCHK = 2 * (qt + 1);
    fetchkv(0);

    for (int c = 0; c < NCHK; c++) {
        if (c + 1 < NCHK) {
            fetchkv(c + 1);
            asm volatile("cp.async.wait_group 1;" ::: "memory");
        } else {
            asm volatile("cp.async.wait_group 0;" ::: "memory");
        }
        __syncthreads();   // chunk c visible (also Q stores on first iter)

        const uint32_t kbuf = smb + OFF_AK + (c & 1) * KCH_B;
        const uint32_t vbuf = smb + OFF_AV + (c & 1) * KCH_B;

        // ---- S = Q . K^T for 32 K-rows (single fp16 pass, k=128) ----
        float s[4][4];
        #pragma unroll
        for (int i = 0; i < 4; i++)
            #pragma unroll
            for (int j = 0; j < 4; j++) s[i][j] = 0.f;

        #pragma unroll
        for (int ks = 0; ks < 8; ks++) {
            uint32_t afr[4];
            ldmx4(afr, smb + (w * 16 + lrow) * AQ_STR + 2 * (ks * 16 + lcol));
            #pragma unroll
            for (int nb = 0; nb < 2; nb++) {
                uint32_t bm[4];
                ldmx4(bm, kbuf + (nb * 16 + lrow) * AQ_STR + 2 * (ks * 16 + lcol));
                mma16816(s[nb * 2],     afr, bm[0], bm[2]);
                mma16816(s[nb * 2 + 1], afr, bm[1], bm[3]);
            }
        }

        // ---- scale + causal mask (only tail chunks can mask) ----
        #pragma unroll
        for (int nt = 0; nt < 4; nt++)
            #pragma unroll
            for (int j = 0; j < 4; j++) s[nt][j] *= SCALE_;
        if (c >= 2 * qt) {
            const int r0 = qt * 64 + w * 16 + (lane >> 2);
            const int r1 = r0 + 8;
            #pragma unroll
            for (int nt = 0; nt < 4; nt++) {
                const int col = c * 32 + nt * 8 + (lane & 3) * 2;
                if (col     > r0) s[nt][0] = NEGF;
                if (col + 1 > r0) s[nt][1] = NEGF;
                if (col     > r1) s[nt][2] = NEGF;
                if (col + 1 > r1) s[nt][3] = NEGF;
            }
        }

        // ---- online softmax (rows r0, r1) ----
        float tm0 = -1e30f, tm1 = -1e30f;
        #pragma unroll
        for (int nt = 0; nt < 4; nt++) {
            tm0 = fmaxf(tm0, fmaxf(s[nt][0], s[nt][1]));
            tm1 = fmaxf(tm1, fmaxf(s[nt][2], s[nt][3]));
        }
        tm0 = fmaxf(tm0, __shfl_xor_sync(~0u, tm0, 1));
        tm0 = fmaxf(tm0, __shfl_xor_sync(~0u, tm0, 2));
        tm1 = fmaxf(tm1, __shfl_xor_sync(~0u, tm1, 1));
        tm1 = fmaxf(tm1, __shfl_xor_sync(~0u, tm1, 2));

        const float mn0 = fmaxf(m0, tm0), mn1 = fmaxf(m1, tm1);
        const float a0 = __expf(m0 - mn0), a1 = __expf(m1 - mn1);
        float rs0 = 0.f, rs1 = 0.f;
        #pragma unroll
        for (int nt = 0; nt < 4; nt++) {
            s[nt][0] = __expf(s[nt][0] - mn0); rs0 += s[nt][0];
            s[nt][1] = __expf(s[nt][1] - mn0); rs0 += s[nt][1];
            s[nt][2] = __expf(s[nt][2] - mn1); rs1 += s[nt][2];
            s[nt][3] = __expf(s[nt][3] - mn1); rs1 += s[nt][3];
        }
        rs0 += __shfl_xor_sync(~0u, rs0, 1); rs0 += __shfl_xor_sync(~0u, rs0, 2);
        rs1 += __shfl_xor_sync(~0u, rs1, 1); rs1 += __shfl_xor_sync(~0u, rs1, 2);
        l0 = l0 * a0 + rs0;  l1 = l1 * a1 + rs1;
        m0 = mn0;            m1 = mn1;
        #pragma unroll
        for (int dt = 0; dt < 16; dt++) {
            accO[dt][0] *= a0; accO[dt][1] *= a0;
            accO[dt][2] *= a1; accO[dt][3] *= a1;
        }

        // ---- P (C-frag -> A-frag, fp16) . V (32 rows, single pass) ----
        #pragma unroll
        for (int kk = 0; kk < 2; kk++) {
            uint32_t ph[4];
            auto mkh = [&](float p0, float p1) -> uint32_t {
                __half2 hp = __floats2half2_rn(p0, p1);
                return *(uint32_t*)&hp;
            };
            ph[0] = mkh(s[2 * kk][0],     s[2 * kk][1]);
            ph[1] = mkh(s[2 * kk][2],     s[2 * kk][3]);
            ph[2] = mkh(s[2 * kk + 1][0], s[2 * kk + 1][1]);
            ph[3] = mkh(s[2 * kk + 1][2], s[2 * kk + 1][3]);
            #pragma unroll
            for (int dt = 0; dt < 8; dt++) {
                uint32_t bm[4];
                ldmx4t(bm, vbuf + (kk * 16 + lrow) * AQ_STR
                            + 2 * (dt * 16 + lcol));
                mma16816(accO[dt * 2],     ph, bm[0], bm[1]);
                mma16816(accO[dt * 2 + 1], ph, bm[2], bm[3]);
            }
        }
        __syncthreads();   // all reads of buffer c&1 done before it is refilled
    }

    // ---- epilogue: normalize, unshift + head-interleave into y ----
    const float i0 = 1.f / l0, i1 = 1.f / l1;
    const int row = w * 16 + (lane >> 2);
    const int np0 = g * GS_ + qt * 64 + row;
    const int np1 = np0 + 8;
    const int nf0 = (h < HALF_) ? np0 : ((np0 + SHIFT_) & (N_ - 1));
    const int nf1 = (h < HALF_) ? np1 : ((np1 + SHIFT_) & (N_ - 1));
    float* y0 = y + ((size_t)b * N_ + nf0) * C_ + h * HD_;
    float* y1 = y + ((size_t)b * N_ + nf1) * C_ + h * HD_;
    #pragma unroll
    for (int dt = 0; dt < 16; dt++) {
        const int d = dt * 8 + (lane & 3) * 2;
        *(float2*)(y0 + d) = make_float2(accO[dt][0] * i0, accO[dt][1] * i0);
        *(float2*)(y1 + d) = make_float2(accO[dt][2] * i1, accO[dt][3] * i1);
    }
}

// ---------------------------------------------------------------------------
extern "C" void kernel_launch(void* const* d_in, const int* in_sizes, int n_in,
                              void* d_out, int out_size)
{
    const float* x  = (const float*)d_in[0];
    const float* Wq = (const float*)d_in[1];
    const float* bq = (const float*)d_in[2];
    const float* Wk = (const float*)d_in[3];
    const float* bk = (const float*)d_in[4];
    const float* Wv = (const float*)d_in[5];
    const float* bv = (const float*)d_in[6];
    float* y = (float*)d_out;

    __half *Ag, *Bg;
    cudaGetSymbolAddress((void**)&Ag, g_A);
    cudaGetSymbolAddress((void**)&Bg, g_B);

    // fp16 splits: A = [Ah|Al], B = [Bh|Bh]
    split_kernel<<<MROWS * 2, 256>>>(x,  Ag, 0);
    split_kernel<<<C_ * 2,    256>>>(Wq, Bg + (size_t)0 * C_ * K4, 1);
    split_kernel<<<C_ * 2,    256>>>(Wk, Bg + (size_t)1 * C_ * K4, 1);
    split_kernel<<<C_ * 2,    256>>>(Wv, Bg + (size_t)2 * C_ * K4, 1);

    // fp16 HMMA projections (2-pass, K=4096)
    cudaFuncSetAttribute(gemm_kernel,
                         cudaFuncAttributeMaxDynamicSharedMemorySize, GM_SMEM);
    gemm_kernel<<<dim3(C_ / 128, MROWS / 128, 3), 256, GM_SMEM>>>(bq, bk, bv);

    // fp16 single-pass FA2 attention (4 CTAs/SM)
    cudaFuncSetAttribute(attn_kernel,
                         cudaFuncAttributeMaxDynamicSharedMemorySize, AT_SMEM);
    attn_kernel<<<dim3(4, G_, B_ * H_), 128, AT_SMEM>>>(y);
}

// round 13
// speedup vs baseline: 3.7475x; 1.8362x over previous
#include <cuda_runtime.h>
#include <cuda_fp16.h>
#include <math.h>
#include <stdint.h>

// ---------------------------------------------------------------------------
// Problem constants
// ---------------------------------------------------------------------------
#define B_    2
#define N_    8192
#define C_    2048
#define H_    16
#define HD_   128
#define GS_   256
#define G_    (N_/GS_)     // 32
#define HALF_ 8
#define SHIFT_ 128
#define SCALE_ 0.08838834764831843f   // 1/sqrt(128)
#define NEGF  -1e9f

#define MROWS (B_*N_)      // 16384

// scratch
__device__ __half g_A[(size_t)MROWS * C_];               // x fp16 [16384][2048]
__device__ __half g_B[(size_t)3 * C_ * C_];              // W fp16 [3][2048][2048]
__device__ __half g_q[(size_t)3 * B_ * H_ * N_ * HD_];   // qkv fp16 (shifted)

// ---------------------------------------------------------------------------
// convert: fp32 -> fp16, dense (one float4 -> two half2 per thread)
// ---------------------------------------------------------------------------
__global__ __launch_bounds__(256) void conv_kernel(
    const float* __restrict__ in, __half* __restrict__ out)
{
    size_t idx = (size_t)blockIdx.x * 256 + threadIdx.x;
    float4 v = ((const float4*)in)[idx];
    __half2* o = (__half2*)(out + idx * 4);
    o[0] = __floats2half2_rn(v.x, v.y);
    o[1] = __floats2half2_rn(v.z, v.w);
}

// ---------------------------------------------------------------------------
// common MMA helpers (fragment idioms proven R5-R12)
// ---------------------------------------------------------------------------
__device__ __forceinline__ uint32_t s2u(const void* p) {
    uint32_t a;
    asm("{ .reg .u64 t; cvta.to.shared.u64 t, %1; cvt.u32.u64 %0, t; }"
        : "=r"(a) : "l"(p));
    return a;
}
__device__ __forceinline__ void ldmx4(uint32_t* r, uint32_t addr) {
    asm volatile("ldmatrix.sync.aligned.m8n8.x4.shared.b16 {%0,%1,%2,%3}, [%4];"
                 : "=r"(r[0]), "=r"(r[1]), "=r"(r[2]), "=r"(r[3]) : "r"(addr));
}
__device__ __forceinline__ void ldmx4t(uint32_t* r, uint32_t addr) {
    asm volatile("ldmatrix.sync.aligned.m8n8.x4.trans.shared.b16 {%0,%1,%2,%3}, [%4];"
                 : "=r"(r[0]), "=r"(r[1]), "=r"(r[2]), "=r"(r[3]) : "r"(addr));
}
__device__ __forceinline__ void mma16816(float* c, const uint32_t* a,
                                         uint32_t b0, uint32_t b1) {
    asm volatile(
        "mma.sync.aligned.m16n8k16.row.col.f32.f16.f16.f32 "
        "{%0,%1,%2,%3}, {%4,%5,%6,%7}, {%8,%9}, {%0,%1,%2,%3};"
        : "+f"(c[0]), "+f"(c[1]), "+f"(c[2]), "+f"(c[3])
        : "r"(a[0]), "r"(a[1]), "r"(a[2]), "r"(a[3]), "r"(b0), "r"(b1));
}
__device__ __forceinline__ void cp16(uint32_t dst, const void* src) {
    asm volatile("cp.async.cg.shared.global [%0], [%1], 16;"
                 :: "r"(dst), "l"(src) : "memory");
}

// ---------------------------------------------------------------------------
// HMMA GEMM (R10-proven pipeline, K=2048 single pass): tile 128x128,
// warp 32x64, KC=64, 3-stage cp.async, 2 CTAs/SM. Epilogue -> fp16 qkv.
// ---------------------------------------------------------------------------
#define KC      64
#define NCH     (C_/KC)        // 32
#define GROWB   144            // 64 fp16 (128 B) + 16 pad (16B-aligned rows)
#define GSTAGE  (256*GROWB)    // 36864 B
#define GM_SMEM (3*GSTAGE)     // 110592 B -> 2 CTAs/SM

__global__ __launch_bounds__(256, 2) void gemm_kernel(
    const float* __restrict__ bq, const float* __restrict__ bk,
    const float* __restrict__ bv)
{
    extern __shared__ char smg[];
    const uint32_t smb = s2u(smg);

    const int tid  = threadIdx.x;
    const int wid  = tid >> 5, lane = tid & 31;
    const int wm   = wid & 3;
    const int wn   = wid >> 2;
    const int lrow = lane & 15;
    const int lcol = (lane >> 4) * 8;

    const int n0 = blockIdx.x * 128;
    const int m0 = blockIdx.y * 128;
    const int z  = blockIdx.z;
    const __half* __restrict__ Ap = g_A + (size_t)m0 * C_;
    const __half* __restrict__ Bp = g_B + (size_t)z * C_ * C_ + (size_t)n0 * C_;
    const float* __restrict__ bias = (z == 0) ? bq : (z == 1) ? bk : bv;

    float acc[2][8][4];
    #pragma unroll
    for (int i = 0; i < 2; i++)
        #pragma unroll
        for (int j = 0; j < 8; j++)
            #pragma unroll
            for (int k = 0; k < 4; k++) acc[i][j][k] = 0.f;

    auto fetch = [&](int c) {
        const int s = c - (c / 3) * 3;
        const size_t k0 = (size_t)c * KC;
        const uint32_t base = smb + s * GSTAGE;
        #pragma unroll
        for (int i = 0; i < 4; i++) {
            int f = tid + 256 * i, row = f >> 3, cc = (f & 7) * 16;
            cp16(base + row * GROWB + cc, Ap + (size_t)row * C_ + k0 + cc / 2);
        }
        #pragma unroll
        for (int i = 0; i < 4; i++) {
            int f = tid + 256 * i, row = f >> 3, cc = (f & 7) * 16;
            cp16(base + 128 * GROWB + row * GROWB + cc,
                 Bp + (size_t)row * C_ + k0 + cc / 2);
        }
        asm volatile("cp.async.commit_group;" ::: "memory");
    };

    fetch(0); fetch(1);

    for (int c = 0; c < NCH; c++) {
        if (c + 1 < NCH) asm volatile("cp.async.wait_group 1;" ::: "memory");
        else             asm volatile("cp.async.wait_group 0;" ::: "memory");
        __syncthreads();
        if (c + 2 < NCH) fetch(c + 2);

        const int s = c - (c / 3) * 3;
        const uint32_t aB = smb + s * GSTAGE;
        const uint32_t bB = aB + 128 * GROWB;
        #pragma unroll
        for (int ks = 0; ks < 4; ks++) {
            const int kb = 2 * (ks * 16 + lcol);
            uint32_t afr[2][4];
            #pragma unroll
            for (int mi = 0; mi < 2; mi++)
                ldmx4(afr[mi], aB + (wm * 32 + mi * 16 + lrow) * GROWB + kb);
            #pragma unroll
            for (int nb = 0; nb < 4; nb++) {
                uint32_t bm[4];
                ldmx4(bm, bB + (wn * 64 + nb * 16 + lrow) * GROWB + kb);
                #pragma unroll
                for (int mi = 0; mi < 2; mi++) {
                    mma16816(acc[mi][2 * nb],     afr[mi], bm[0], bm[2]);
                    mma16816(acc[mi][2 * nb + 1], afr[mi], bm[1], bm[3]);
                }
            }
        }
    }

    // epilogue: fragments -> g_q (bias + shift), fp16
    const size_t PSZ = (size_t)B_ * H_ * N_ * HD_;
    __half* qp = g_q + (size_t)z * PSZ;
    const int qrow = lane >> 2;
    const int qcol = (lane & 3) * 2;

    #pragma unroll
    for (int mi = 0; mi < 2; mi++) {
        #pragma unroll
        for (int hf = 0; hf < 2; hf++) {
            const int m  = m0 + wm * 32 + mi * 16 + qrow + hf * 8;
            const int b  = m >> 13;
            const int ns = m & (N_ - 1);
            #pragma unroll
            for (int ni = 0; ni < 8; ni++) {
                const int n = n0 + wn * 64 + ni * 8 + qcol;
                const int hh = n >> 7;
                const int d  = n & (HD_ - 1);
                const int nd = (hh < HALF_) ? ns : ((ns - SHIFT_) & (N_ - 1));
                const size_t off = (((size_t)b * H_ + hh) * N_ + nd) * HD_ + d;
                float v0 = acc[mi][ni][hf * 2 + 0] + bias[n];
                float v1 = acc[mi][ni][hf * 2 + 1] + bias[n + 1];
                *(__half2*)(qp + off) = __floats2half2_rn(v0, v1);
            }
        }
    }
}

// ---------------------------------------------------------------------------
// FA2-style fp16 attention (proven R12): CTA = (qt, g, b*h), 128 thr, 4 warps,
// 4 CTAs/SM. Single-pass QK and PV. 32-row K/V chunks, double-buffered.
// ---------------------------------------------------------------------------
#define AQ_STR  272
#define KCH_B   (32*AQ_STR)         // 8704 per chunk buffer
#define OFF_AK  (64*AQ_STR)         // 17408 (after Q)
#define OFF_AV  (OFF_AK + 2*KCH_B)  // 34816
#define AT_SMEM (OFF_AV + 2*KCH_B)  // 52224 -> 4 CTAs/SM

__global__ __launch_bounds__(128, 4) void attn_kernel(float* __restrict__ y)
{
    extern __shared__ char smc[];
    const uint32_t smb = s2u(smc);
    const int tid  = threadIdx.x;
    const int w    = tid >> 5, lane = tid & 31;
    const int lrow = lane & 15, lcol = (lane >> 4) * 8;

    const int qt = blockIdx.x;               // 0..3
    const int g  = blockIdx.y;               // 0..31
    const int bh = blockIdx.z;
    const int b  = bh >> 4;
    const int h  = bh & 15;

    const size_t TOT   = (size_t)B_ * H_ * N_ * HD_;
    const size_t plane = ((size_t)b * H_ + h) * (size_t)N_ * HD_;
    const __half* qp = g_q + plane + (size_t)(g * GS_ + qt * 64) * HD_;
    const __half* kp = g_q + TOT     + plane + (size_t)(g * GS_) * HD_;
    const __half* vp = g_q + 2 * TOT + plane + (size_t)(g * GS_) * HD_;

    // load Q tile: 64 rows x 256 B
    #pragma unroll
    for (int i = 0; i < 8; i++) {
        int f = tid + 128 * i, r = f >> 4, c8 = (f & 15) * 8;
        *(uint4*)(smc + r * AQ_STR + 2 * c8) =
            *(const uint4*)(qp + (size_t)r * HD_ + c8);
    }

    // async fetch of 32-row K/V chunk c into buffer c&1
    auto fetchkv = [&](int c) {
        const int bsel = c & 1;
        const uint32_t kb = smb + OFF_AK + bsel * KCH_B;
        const uint32_t vb = smb + OFF_AV + bsel * KCH_B;
        #pragma unroll
        for (int i = 0; i < 4; i++) {
            int f = tid + 128 * i;
            int r = f >> 4;
            int u = f & 15;
            const size_t row = (size_t)(c * 32 + r) * HD_;
            cp16(kb + r * AQ_STR + u * 16, kp + row + u * 8);
        }
        #pragma unroll
        for (int i = 0; i < 4; i++) {
            int f = tid + 128 * i;
            int r = f >> 4;
            int u = f & 15;
            const size_t row = (size_t)(c * 32 + r) * HD_;
            cp16(vb + r * AQ_STR + u * 16, vp + row + u * 8);
        }
        asm volatile("cp.async.commit_group;" ::: "memory");
    };

    float m0 = -1e30f, m1 = -1e30f, l0 = 0.f, l1 = 0.f;
    float accO[16][4];
    #pragma unroll
    for (int i = 0; i < 16; i++)
        #pragma unroll
        for (int j = 0; j < 4; j++) accO[i][j] = 0.f;

    const int NCHK = 2 * (qt + 1);
    fetchkv(0);

    for (int c = 0; c < NCHK; c++) {
        if (c + 1 < NCHK) {
            fetchkv(c + 1);
            asm volatile("cp.async.wait_group 1;" ::: "memory");
        } else {
            asm volatile("cp.async.wait_group 0;" ::: "memory");
        }
        __syncthreads();   // chunk c visible (also Q stores on first iter)

        const uint32_t kbuf = smb + OFF_AK + (c & 1) * KCH_B;
        const uint32_t vbuf = smb + OFF_AV + (c & 1) * KCH_B;

        // ---- S = Q . K^T for 32 K-rows (single fp16 pass, k=128) ----
        float s[4][4];
        #pragma unroll
        for (int i = 0; i < 4; i++)
            #pragma unroll
            for (int j = 0; j < 4; j++) s[i][j] = 0.f;

        #pragma unroll
        for (int ks = 0; ks < 8; ks++) {
            uint32_t afr[4];
            ldmx4(afr, smb + (w * 16 + lrow) * AQ_STR + 2 * (ks * 16 + lcol));
            #pragma unroll
            for (int nb = 0; nb < 2; nb++) {
                uint32_t bm[4];
                ldmx4(bm, kbuf + (nb * 16 + lrow) * AQ_STR + 2 * (ks * 16 + lcol));
                mma16816(s[nb * 2],     afr, bm[0], bm[2]);
                mma16816(s[nb * 2 + 1], afr, bm[1], bm[3]);
            }
        }

        // ---- scale + causal mask (only tail chunks can mask) ----
        #pragma unroll
        for (int nt = 0; nt < 4; nt++)
            #pragma unroll
            for (int j = 0; j < 4; j++) s[nt][j] *= SCALE_;
        if (c >= 2 * qt) {
            const int r0 = qt * 64 + w * 16 + (lane >> 2);
            const int r1 = r0 + 8;
            #pragma unroll
            for (int nt = 0; nt < 4; nt++) {
                const int col = c * 32 + nt * 8 + (lane & 3) * 2;
                if (col     > r0) s[nt][0] = NEGF;
                if (col + 1 > r0) s[nt][1] = NEGF;
                if (col     > r1) s[nt][2] = NEGF;
                if (col + 1 > r1) s[nt][3] = NEGF;
            }
        }

        // ---- online softmax (rows r0, r1) ----
        float tm0 = -1e30f, tm1 = -1e30f;
        #pragma unroll
        for (int nt = 0; nt < 4; nt++) {
            tm0 = fmaxf(tm0, fmaxf(s[nt][0], s[nt][1]));
            tm1 = fmaxf(tm1, fmaxf(s[nt][2], s[nt][3]));
        }
        tm0 = fmaxf(tm0, __shfl_xor_sync(~0u, tm0, 1));
        tm0 = fmaxf(tm0, __shfl_xor_sync(~0u, tm0, 2));
        tm1 = fmaxf(tm1, __shfl_xor_sync(~0u, tm1, 1));
        tm1 = fmaxf(tm1, __shfl_xor_sync(~0u, tm1, 2));

        const float mn0 = fmaxf(m0, tm0), mn1 = fmaxf(m1, tm1);
        const float a0 = __expf(m0 - mn0), a1 = __expf(m1 - mn1);
        float rs0 = 0.f, rs1 = 0.f;
        #pragma unroll
        for (int nt = 0; nt < 4; nt++) {
            s[nt][0] = __expf(s[nt][0] - mn0); rs0 += s[nt][0];
            s[nt][1] = __expf(s[nt][1] - mn0); rs0 += s[nt][1];
            s[nt][2] = __expf(s[nt][2] - mn1); rs1 += s[nt][2];
            s[nt][3] = __expf(s[nt][3] - mn1); rs1 += s[nt][3];
        }
        rs0 += __shfl_xor_sync(~0u, rs0, 1); rs0 += __shfl_xor_sync(~0u, rs0, 2);
        rs1 += __shfl_xor_sync(~0u, rs1, 1); rs1 += __shfl_xor_sync(~0u, rs1, 2);
        l0 = l0 * a0 + rs0;  l1 = l1 * a1 + rs1;
        m0 = mn0;            m1 = mn1;
        #pragma unroll
        for (int dt = 0; dt < 16; dt++) {
            accO[dt][0] *= a0; accO[dt][1] *= a0;
            accO[dt][2] *= a1; accO[dt][3] *= a1;
        }

        // ---- P (C-frag -> A-frag, fp16) . V (32 rows, single pass) ----
        #pragma unroll
        for (int kk = 0; kk < 2; kk++) {
            uint32_t ph[4];
            auto mkh = [&](float p0, float p1) -> uint32_t {
                __half2 hp = __floats2half2_rn(p0, p1);
                return *(uint32_t*)&hp;
            };
            ph[0] = mkh(s[2 * kk][0],     s[2 * kk][1]);
            ph[1] = mkh(s[2 * kk][2],     s[2 * kk][3]);
            ph[2] = mkh(s[2 * kk + 1][0], s[2 * kk + 1][1]);
            ph[3] = mkh(s[2 * kk + 1][2], s[2 * kk + 1][3]);
            #pragma unroll
            for (int dt = 0; dt < 8; dt++) {
                uint32_t bm[4];
                ldmx4t(bm, vbuf + (kk * 16 + lrow) * AQ_STR
                            + 2 * (dt * 16 + lcol));
                mma16816(accO[dt * 2],     ph, bm[0], bm[1]);
                mma16816(accO[dt * 2 + 1], ph, bm[2], bm[3]);
            }
        }
        __syncthreads();   // all reads of buffer c&1 done before it is refilled
    }

    // ---- epilogue: normalize, unshift + head-interleave into y ----
    const float i0 = 1.f / l0, i1 = 1.f / l1;
    const int row = w * 16 + (lane >> 2);
    const int np0 = g * GS_ + qt * 64 + row;
    const int np1 = np0 + 8;
    const int nf0 = (h < HALF_) ? np0 : ((np0 + SHIFT_) & (N_ - 1));
    const int nf1 = (h < HALF_) ? np1 : ((np1 + SHIFT_) & (N_ - 1));
    float* y0 = y + ((size_t)b * N_ + nf0) * C_ + h * HD_;
    float* y1 = y + ((size_t)b * N_ + nf1) * C_ + h * HD_;
    #pragma unroll
    for (int dt = 0; dt < 16; dt++) {
        const int d = dt * 8 + (lane & 3) * 2;
        *(float2*)(y0 + d) = make_float2(accO[dt][0] * i0, accO[dt][1] * i0);
        *(float2*)(y1 + d) = make_float2(accO[dt][2] * i1, accO[dt][3] * i1);
    }
}

// ---------------------------------------------------------------------------
extern "C" void kernel_launch(void* const* d_in, const int* in_sizes, int n_in,
                              void* d_out, int out_size)
{
    const float* x  = (const float*)d_in[0];
    const float* Wq = (const float*)d_in[1];
    const float* bq = (const float*)d_in[2];
    const float* Wk = (const float*)d_in[3];
    const float* bk = (const float*)d_in[4];
    const float* Wv = (const float*)d_in[5];
    const float* bv = (const float*)d_in[6];
    float* y = (float*)d_out;

    __half *Ag, *Bg;
    cudaGetSymbolAddress((void**)&Ag, g_A);
    cudaGetSymbolAddress((void**)&Bg, g_B);

    // fp16 converts (dense)
    conv_kernel<<<(MROWS * C_ / 4) / 256, 256>>>(x,  Ag);
    conv_kernel<<<(C_ * C_ / 4) / 256, 256>>>(Wq, Bg + (size_t)0 * C_ * C_);
    conv_kernel<<<(C_ * C_ / 4) / 256, 256>>>(Wk, Bg + (size_t)1 * C_ * C_);
    conv_kernel<<<(C_ * C_ / 4) / 256, 256>>>(Wv, Bg + (size_t)2 * C_ * C_);

    // fp16 HMMA projections (single pass, K=2048)
    cudaFuncSetAttribute(gemm_kernel,
                         cudaFuncAttributeMaxDynamicSharedMemorySize, GM_SMEM);
    gemm_kernel<<<dim3(C_ / 128, MROWS / 128, 3), 256, GM_SMEM>>>(bq, bk, bv);

    // fp16 single-pass FA2 attention (4 CTAs/SM)
    cudaFuncSetAttribute(attn_kernel,
                         cudaFuncAttributeMaxDynamicSharedMemorySize, AT_SMEM);
    attn_kernel<<<dim3(4, G_, B_ * H_), 128, AT_SMEM>>>(y);
}